// round 13
// baseline (speedup 1.0000x reference)
#include <cuda_runtime.h>
#include <cuda_fp16.h>
#include <math.h>
#include <stdint.h>

#define NN   100000
#define EE   1600000
#define HID  128
#define HEADS 4
#define NEG  0.2f
#define LNEPS 1e-5f
#define NB   391           // (NN+255)/256
#define AGB  12500         // NN/8 warp-per-node blocks

// ---------------- device scratch ----------------
__device__ __align__(256) float  g_h   [(size_t)NN*HID];
__device__ __align__(256) __half g_h16 [(size_t)NN*HID];   // fp16 copy for e8 gather
__device__ __align__(256) __half g_g16 [(size_t)NN*HID];   // fp16 GAT features
__device__ __align__(256) float  g_agg [(size_t)NN*HID];
__device__ __align__(256) float  g_xgat[(size_t)NN*HID];
__device__ __align__(256) float  g_z   [(size_t)NN*HID];
__device__ __align__(256) float  g_M   [HID*HID];          // Wf1 @ W_e8
__device__ __align__(16)  float  g_asrc[(size_t)NN*HEADS];
__device__ __align__(16)  float  g_adst[(size_t)NN*HEADS];
__device__ float g_dinv[NN];
__device__ int   g_cnt_row[NN];
__device__ int   g_cnt_col[NN];
__device__ int   g_rptr[NN+1];
__device__ int   g_cptr[NN+1];
__device__ int   g_rcur[NN];
__device__ int   g_ccur[NN];
__device__ int   g_csr_rc[EE];
__device__ int   g_csr_cs[EE];
__device__ int   g_part[2*NB];
__device__ int   g_shift;

// ---------------- helpers ----------------
__device__ __forceinline__ float wsum(float x){
    #pragma unroll
    for (int o=16;o;o>>=1) x += __shfl_xor_sync(0xffffffffu, x, o);
    return x;
}
__device__ __forceinline__ int wsumi(int x){
    #pragma unroll
    for (int o=16;o;o>>=1) x += __shfl_xor_sync(0xffffffffu, x, o);
    return x;
}
__device__ __forceinline__ float lrelu(float x){ return x > 0.f ? x : NEG * x; }

typedef unsigned long long ull;
__device__ __forceinline__ ull pack2(float x, float y){
    ull r; asm("mov.b64 %0, {%1,%2};" : "=l"(r) : "f"(x), "f"(y)); return r;
}
__device__ __forceinline__ void unpack2(ull v, float &x, float &y){
    asm("mov.b64 {%0,%1}, %2;" : "=f"(x), "=f"(y) : "l"(v));
}
__device__ __forceinline__ void ffma2(ull &d, ull a, ull b){
    asm("fma.rn.f32x2 %0, %1, %2, %0;" : "+l"(d) : "l"(a), "l"(b));
}
// gather 4 halves (dims 4l..4l+3) and accumulate into float4
__device__ __forceinline__ void gather_h4(const __half* base, size_t row, int lane,
                                          float w, float4 &acc){
    uint2 u = ((const uint2*)(base + row*HID))[lane];
    float2 f01 = __half22float2(*(const __half2*)&u.x);
    float2 f23 = __half22float2(*(const __half2*)&u.y);
    acc.x = fmaf(w, f01.x, acc.x);
    acc.y = fmaf(w, f01.y, acc.y);
    acc.z = fmaf(w, f23.x, acc.z);
    acc.w = fmaf(w, f23.y, acc.w);
}

// ---------------- init ----------------
__global__ void kInit(const int* ei){
    if (blockIdx.x == 0){
        if (threadIdx.x == 0){
            int acc = 0;
            #pragma unroll 1
            for (int i = 1; i < 128; i += 2) acc |= ei[i];
            g_shift = (acc == 0) ? 1 : 0;
        }
    } else {
        int i = (blockIdx.x-1)*256 + threadIdx.x;
        if (i < NN){ g_cnt_row[i]=0; g_cnt_col[i]=0; }
    }
}

// ---------------- small weight-fold: g_M = Wf1 @ W_e8 ----------------
__global__ void kSmallMM(const float* __restrict__ Wfus, const float* __restrict__ We8){
    int tid = threadIdx.x;
    int half = tid >> 7, k = tid & 127;
    int c = blockIdx.x*2 + half;
    float acc = 0.f;
    #pragma unroll 8
    for (int j = 0; j < 128; j++)
        acc = fmaf(Wfus[c*256 + j], We8[j*128 + k], acc);
    g_M[c*128 + k] = acc;
}

// ---------------- edge loads (x4 vectorized) ----------------
__device__ __forceinline__ void load_edges4(const int* ei, int e0, int sh, int* r, int* c){
    if (sh == 0){
        int4 rr = *(const int4*)(ei + e0);
        int4 cc = *(const int4*)(ei + (size_t)EE + e0);
        r[0]=rr.x; r[1]=rr.y; r[2]=rr.z; r[3]=rr.w;
        c[0]=cc.x; c[1]=cc.y; c[2]=cc.z; c[3]=cc.w;
    } else {
        int4 a = *(const int4*)(ei + 2*(size_t)e0);
        int4 b = *(const int4*)(ei + 2*(size_t)e0 + 4);
        r[0]=a.x; r[1]=a.z; r[2]=b.x; r[3]=b.z;
        int4 d = *(const int4*)(ei + 2*(size_t)EE + 2*(size_t)e0);
        int4 f = *(const int4*)(ei + 2*(size_t)EE + 2*(size_t)e0 + 4);
        c[0]=d.x; c[1]=d.z; c[2]=f.x; c[3]=f.z;
    }
}

__global__ void k_hist(const int* ei){
    int e0 = (blockIdx.x*blockDim.x + threadIdx.x)*4;
    if (e0 >= EE) return;
    int r[4], c[4];
    load_edges4(ei, e0, g_shift, r, c);
    #pragma unroll
    for (int j = 0; j < 4; j++){
        atomicAdd(&g_cnt_row[r[j]], 1);
        atomicAdd(&g_cnt_col[c[j]], 1);
    }
}

__global__ void k_fill(const int* ei){
    int e0 = (blockIdx.x*blockDim.x + threadIdx.x)*4;
    if (e0 >= EE) return;
    int r[4], c[4];
    load_edges4(ei, e0, g_shift, r, c);
    #pragma unroll
    for (int j = 0; j < 4; j++){
        int p = atomicAdd(&g_rcur[r[j]], 1);
        g_csr_rc[p] = c[j];
        int q = atomicAdd(&g_ccur[c[j]], 1);
        g_csr_cs[q] = r[j];
    }
}

// ---------------- scan ----------------
__global__ void kScanP1Dinv(){
    int t = blockIdx.x;
    if (t < 2*NB){
        const int* cnt = (t < NB) ? g_cnt_row : g_cnt_col;
        int i = ((t < NB) ? t : t - NB)*256 + threadIdx.x;
        int v = (i < NN) ? cnt[i] : 0;
        int ws = wsumi(v);
        __shared__ int sums[8];
        int lane = threadIdx.x & 31, warp = threadIdx.x >> 5;
        if (lane == 0) sums[warp] = ws;
        __syncthreads();
        if (threadIdx.x == 0){
            int s = 0;
            #pragma unroll
            for (int w = 0; w < 8; w++) s += sums[w];
            g_part[t] = s;
        }
    } else {
        int i = (t - 2*NB)*256 + threadIdx.x;
        if (i < NN){
            int d = g_cnt_col[i];
            g_dinv[i] = d > 0 ? rsqrtf((float)d) : 0.f;
        }
    }
}

__global__ __launch_bounds__(1024)
void kScanP2(){
    __shared__ int sh[1024];
    int tid = threadIdx.x;
    int half = tid >> 9, li = tid & 511;
    int idx = half ? NB + li : li;
    int v = (li < NB) ? g_part[idx] : 0;
    sh[tid] = v; __syncthreads();
    #pragma unroll
    for (int off = 1; off < 512; off <<= 1){
        int y = (li >= off) ? sh[tid - off] : 0;
        __syncthreads();
        sh[tid] += y;
        __syncthreads();
    }
    if (li < NB) g_part[idx] = sh[tid] - v;
    if (tid == 0){ g_rptr[NN] = EE; g_cptr[NN] = EE; }
}

__global__ void kScanP3(){
    int t = blockIdx.x;
    int isrow = (t < NB);
    const int* cnt = isrow ? g_cnt_row : g_cnt_col;
    int* ptr = isrow ? g_rptr : g_cptr;
    int* cur = isrow ? g_rcur : g_ccur;
    int i = (isrow ? t : t - NB)*256 + threadIdx.x;
    int v = (i < NN) ? cnt[i] : 0;
    int lane = threadIdx.x & 31, warp = threadIdx.x >> 5;
    int x = v;
    #pragma unroll
    for (int o=1;o<32;o<<=1){
        int y = __shfl_up_sync(0xffffffffu, x, o);
        if (lane >= o) x += y;
    }
    __shared__ int sums[8];
    __shared__ int offs[8];
    if (lane == 31) sums[warp] = x;
    __syncthreads();
    if (threadIdx.x == 0){
        int s = 0;
        #pragma unroll
        for (int w = 0; w < 8; w++){ offs[w] = s; s += sums[w]; }
    }
    __syncthreads();
    int ex = x - v + offs[warp] + g_part[t];
    if (i < NN){ ptr[i] = ex; cur[i] = ex; }
}

// ---------------- FFMA2 GEMM (R8 config) ----
// EPI: 0 plain, 1 residual+LN+ReLU, 2 plain + attention logits
// A16OUT: if nonzero, the A-load loop also emits __half copy of A into A16 (KTOT=128 only).
// C may be null (fp16-only output); C16 may be null.
#define WPAD 129
#define APAD 66
#define SMEMB ((64*WPAD + 64*APAD)*4)
template<int KTOT, int EPI, int A16OUT>
__global__ __launch_bounds__(256)
void k_gemm(const float* __restrict__ A0, const float* __restrict__ A1,
            const float* __restrict__ W,  const float* __restrict__ W2,
            const float* __restrict__ bias,
            const float* __restrict__ res, const float* __restrict__ gamma,
            const float* __restrict__ beta, float* __restrict__ C,
            __half* __restrict__ C16, __half* __restrict__ A16,
            const float* __restrict__ att_s, const float* __restrict__ att_d)
{
    extern __shared__ float smem[];
    float* Ws = smem;                 // [64][WPAD]
    float* As = smem + 64*WPAD;       // [64][APAD]
    int tid  = threadIdx.x;
    int row0 = blockIdx.x * 64;
    int lane = tid & 31, warp = tid >> 5;
    int r0 = warp * 8;

    ull acc[4][4];
    #pragma unroll
    for (int p = 0; p < 4; p++)
        #pragma unroll
        for (int j = 0; j < 4; j++){
            float b = bias ? bias[lane + 32*j] : 0.f;
            acc[p][j] = pack2(b, b);
        }

    const int NCH = KTOT / 64;
    #pragma unroll
    for (int ch = 0; ch < NCH; ch++){
        const float* A = (KTOT == 256 && ch >= 2) ? A1 : A0;
        int acol = (KTOT == 256) ? (ch & 1)*64 : ch*64;
        const float* Wp; int wstride, woff;
        if (KTOT == 256 && ch >= 2){ Wp = W2; wstride = 256; woff = 128 + (ch-2)*64; }
        else                       { Wp = W;  wstride = 128; woff = (ch & 1)*64; }
        for (int idx = tid; idx < 128*64; idx += 256){
            int o = idx >> 6, k = idx & 63;
            Ws[k*WPAD + o] = Wp[(size_t)o*wstride + woff + k];
        }
        for (int idx = tid; idx < 64*64; idx += 256){
            int r = idx >> 6, k = idx & 63;
            int gr = row0 + r;
            float v = (gr < NN) ? A[(size_t)gr*128 + acol + k] : 0.f;
            As[k*APAD + r] = v;
            if (A16OUT && gr < NN)
                A16[(size_t)gr*128 + acol + k] = __float2half(v);
        }
        __syncthreads();

        #pragma unroll 2
        for (int k = 0; k < 64; k++){
            const float* wr = Ws + k*WPAD + lane;
            ull w0 = pack2(wr[0],  wr[0]);
            ull w1 = pack2(wr[32], wr[32]);
            ull w2 = pack2(wr[64], wr[64]);
            ull w3 = pack2(wr[96], wr[96]);
            const ull* ar = (const ull*)(As + k*APAD + r0);
            ull a0 = ar[0], a1 = ar[1], a2 = ar[2], a3 = ar[3];
            ffma2(acc[0][0], a0, w0); ffma2(acc[0][1], a0, w1);
            ffma2(acc[0][2], a0, w2); ffma2(acc[0][3], a0, w3);
            ffma2(acc[1][0], a1, w0); ffma2(acc[1][1], a1, w1);
            ffma2(acc[1][2], a1, w2); ffma2(acc[1][3], a1, w3);
            ffma2(acc[2][0], a2, w0); ffma2(acc[2][1], a2, w1);
            ffma2(acc[2][2], a2, w2); ffma2(acc[2][3], a2, w3);
            ffma2(acc[3][0], a3, w0); ffma2(acc[3][1], a3, w1);
            ffma2(acc[3][2], a3, w2); ffma2(acc[3][3], a3, w3);
        }
        __syncthreads();
    }

    float as_[4], ad_[4];
    if (EPI == 2){
        #pragma unroll
        for (int j = 0; j < 4; j++){ as_[j] = att_s[j*32+lane]; ad_[j] = att_d[j*32+lane]; }
    }

    #pragma unroll
    for (int p = 0; p < 4; p++){
        float v0[4], v1[4];
        #pragma unroll
        for (int j = 0; j < 4; j++) unpack2(acc[p][j], v0[j], v1[j]);
        #pragma unroll
        for (int half = 0; half < 2; half++){
            float* v = half ? v1 : v0;
            int gr = row0 + r0 + 2*p + half;
            if (gr >= NN) continue;
            if (EPI != 1){
                if (C){
                    #pragma unroll
                    for (int j = 0; j < 4; j++)
                        C[(size_t)gr*128 + lane + 32*j] = v[j];
                }
                if (C16){
                    #pragma unroll
                    for (int j = 0; j < 4; j++)
                        C16[(size_t)gr*128 + lane + 32*j] = __float2half(v[j]);
                }
                if (EPI == 2){
                    #pragma unroll
                    for (int j = 0; j < 4; j++){
                        float sj = wsum(v[j]*as_[j]);
                        float dj = wsum(v[j]*ad_[j]);
                        if (lane == 0){
                            g_asrc[(size_t)gr*4+j] = sj;
                            g_adst[(size_t)gr*4+j] = dj;
                        }
                    }
                }
            } else {
                #pragma unroll
                for (int j = 0; j < 4; j++)
                    v[j] += res[(size_t)gr*128 + lane + 32*j];
                float s = v[0]+v[1]+v[2]+v[3];
                float mu = wsum(s) * (1.f/128.f);
                float q = 0.f;
                #pragma unroll
                for (int j = 0; j < 4; j++){ float d = v[j]-mu; q = fmaf(d,d,q); }
                float sc = rsqrtf(wsum(q) * (1.f/128.f) + LNEPS);
                #pragma unroll
                for (int j = 0; j < 4; j++){
                    int c = lane + 32*j;
                    float o = (v[j]-mu)*sc*gamma[c] + beta[c];
                    C[(size_t)gr*128 + c] = fmaxf(o, 0.f);
                }
            }
        }
    }
}

// ---------------- E8 aggregation body (fp16 gathers) ----------------
__device__ __forceinline__ void e8agg_body(int bid){
    int w = bid*8 + (threadIdx.x >> 5);
    if (w >= NN) return;
    int lane = threadIdx.x & 31;
    int s = g_rptr[w], e = g_rptr[w+1];
    float4 acc = make_float4(0.f,0.f,0.f,0.f);
    #pragma unroll 2
    for (int i = s; i < e; i++){
        int c = g_csr_rc[i];
        gather_h4(g_h16, (size_t)c, lane, g_dinv[c], acc);
    }
    float du = g_dinv[w];
    float4 o = make_float4(du*acc.x, du*acc.y, du*acc.z, du*acc.w);
    ((float4*)(g_agg + (size_t)w*128))[lane] = o;
}

// ---------------- GAT body (online softmax, fp16 feature gathers) ----------
__device__ __forceinline__ void gat_body(int bid, const float* __restrict__ bgat){
    int v = bid*8 + (threadIdx.x >> 5);
    if (v >= NN) return;
    int lane = threadIdx.x & 31;
    int s = g_cptr[v], e = g_cptr[v+1];

    float4 ad = ((const float4*)g_adst)[v];
    float4 asl = ((const float4*)g_asrc)[v];
    float es[4] = { lrelu(asl.x + ad.x), lrelu(asl.y + ad.y),
                    lrelu(asl.z + ad.z), lrelu(asl.w + ad.w) };

    float m[4]  = { es[0], es[1], es[2], es[3] };
    float sm[4] = { 0.f, 0.f, 0.f, 0.f };
    for (int i = s + lane; i < e; i += 32){
        int u = g_csr_cs[i];
        float4 a = ((const float4*)g_asrc)[u];
        float ev[4] = { lrelu(a.x + ad.x), lrelu(a.y + ad.y),
                        lrelu(a.z + ad.z), lrelu(a.w + ad.w) };
        #pragma unroll
        for (int j = 0; j < 4; j++){
            float mn = fmaxf(m[j], ev[j]);
            sm[j] = sm[j]*__expf(m[j]-mn) + __expf(ev[j]-mn);
            m[j] = mn;
        }
    }
    #pragma unroll
    for (int j = 0; j < 4; j++){
        float mj = m[j], sj = sm[j];
        #pragma unroll
        for (int o = 16; o; o >>= 1){
            float m2 = __shfl_xor_sync(0xffffffffu, mj, o);
            float s2 = __shfl_xor_sync(0xffffffffu, sj, o);
            float mn = fmaxf(mj, m2);
            sj = sj*__expf(mj-mn) + s2*__expf(m2-mn);
            mj = mn;
        }
        sj += __expf(es[j]-mj);
        m[j] = mj;
        sm[j] = 1.f/(sj + 1e-16f);
    }

    int hidx = lane >> 3;
    float adh = (hidx==0)?ad.x : (hidx==1)?ad.y : (hidx==2)?ad.z : ad.w;
    float mh  = m[hidx];
    float ih  = sm[hidx];
    float esh = es[hidx];

    float4 acc = make_float4(0.f,0.f,0.f,0.f);
    #pragma unroll 2
    for (int i = s; i < e; i++){
        int u = g_csr_cs[i];
        float a = g_asrc[(size_t)u*4 + hidx];
        float alpha = __expf(lrelu(a + adh) - mh) * ih;
        gather_h4(g_g16, (size_t)u, lane, alpha, acc);
    }
    {
        float alpha = __expf(esh - mh) * ih;
        gather_h4(g_g16, (size_t)v, lane, alpha, acc);
    }
    float4 b = ((const float4*)bgat)[lane];
    acc.x += b.x; acc.y += b.y; acc.z += b.z; acc.w += b.w;
    ((float4*)(g_xgat + (size_t)v*128))[lane] = acc;
}

// fused: both warp-per-node, 0 smem, same register class
__global__ __launch_bounds__(256)
void kAggGat(const float* __restrict__ bgat){
    if (blockIdx.x < AGB) gat_body(blockIdx.x, bgat);
    else                  e8agg_body(blockIdx.x - AGB);
}

// ---------------- fused readout ----------------
__global__ __launch_bounds__(1024)
void k_readout(const float* __restrict__ Wr1, const float* __restrict__ br1,
               const float* __restrict__ Wr2, const float* __restrict__ br2,
               float* __restrict__ out)
{
    __shared__ ull Ws2[128*32];
    int tid = threadIdx.x;
    for (int idx = tid; idx < 128*32; idx += 1024){
        int k = idx >> 5, o = idx & 31;
        Ws2[idx] = pack2(Wr1[(size_t)o*128 + k], Wr1[(size_t)(o+32)*128 + k]);
    }
    __syncthreads();
    int warp = tid >> 5, lane = tid & 31;
    int node = blockIdx.x*32 + warp;
    if (node >= NN) return;

    float4 zv = ((const float4*)(g_z + (size_t)node*128))[lane];
    ull acc = pack2(br1[lane], br1[lane+32]);
    #pragma unroll 8
    for (int kb = 0; kb < 32; kb++){
        float zx = __shfl_sync(0xffffffffu, zv.x, kb);
        float zy = __shfl_sync(0xffffffffu, zv.y, kb);
        float zz = __shfl_sync(0xffffffffu, zv.z, kb);
        float zw = __shfl_sync(0xffffffffu, zv.w, kb);
        int k = kb*4;
        ffma2(acc, pack2(zx,zx), Ws2[(k+0)*32+lane]);
        ffma2(acc, pack2(zy,zy), Ws2[(k+1)*32+lane]);
        ffma2(acc, pack2(zz,zz), Ws2[(k+2)*32+lane]);
        ffma2(acc, pack2(zw,zw), Ws2[(k+3)*32+lane]);
    }
    float a0, a1; unpack2(acc, a0, a1);
    float r0 = fmaxf(a0, 0.f);
    float r1 = fmaxf(a1, 0.f);
    float p = fmaf(r0, Wr2[lane], r1 * Wr2[lane+32]);
    p = wsum(p);
    if (lane == 0){
        float xv = p + br2[0];
        out[node] = 1.f / (1.f + __expf(-xv));
    }
}

// ---------------- host ----------------
extern "C" void kernel_launch(void* const* d_in, const int* in_sizes, int n_in,
                              void* d_out, int out_size)
{
    const float* x       = (const float*)d_in[0];
    const int*   ei      = (const int*)  d_in[1];
    const float* W_emb   = (const float*)d_in[2];
    const float* b_emb   = (const float*)d_in[3];
    const float* W_e8    = (const float*)d_in[4];
    const float* W_gat   = (const float*)d_in[5];
    const float* att_src = (const float*)d_in[6];
    const float* att_dst = (const float*)d_in[7];
    const float* b_gat   = (const float*)d_in[8];
    const float* W_fus   = (const float*)d_in[9];
    const float* b_fus   = (const float*)d_in[10];
    const float* gamma   = (const float*)d_in[11];
    const float* beta    = (const float*)d_in[12];
    const float* W_r1    = (const float*)d_in[13];
    const float* b_r1    = (const float*)d_in[14];
    const float* W_r2    = (const float*)d_in[15];
    const float* b_r2    = (const float*)d_in[16];
    float* out = (float*)d_out;

    float *h, *agg, *xgat, *z, *Mm;
    __half *h16, *g16;
    cudaGetSymbolAddress((void**)&h,    g_h);
    cudaGetSymbolAddress((void**)&h16,  g_h16);
    cudaGetSymbolAddress((void**)&g16,  g_g16);
    cudaGetSymbolAddress((void**)&agg,  g_agg);
    cudaGetSymbolAddress((void**)&xgat, g_xgat);
    cudaGetSymbolAddress((void**)&z,    g_z);
    cudaGetSymbolAddress((void**)&Mm,   g_M);

    cudaFuncSetAttribute((void*)k_gemm<128,0,0>, cudaFuncAttributeMaxDynamicSharedMemorySize, SMEMB);
    cudaFuncSetAttribute((void*)k_gemm<128,2,1>, cudaFuncAttributeMaxDynamicSharedMemorySize, SMEMB);
    cudaFuncSetAttribute((void*)k_gemm<256,1,0>, cudaFuncAttributeMaxDynamicSharedMemorySize, SMEMB);

    const int gB = (NN + 63) / 64;

    kInit       <<<1 + NB, 256>>>(ei);                         // 0
    k_hist      <<<(EE/4+255)/256, 256>>>(ei);                 // 1
    kSmallMM    <<<64, 256>>>(W_fus, W_e8);                    // 2
    k_gemm<128,0,0><<<gB, 256, SMEMB>>>(x, nullptr, W_emb, nullptr, b_emb,
            nullptr, nullptr, nullptr, h, nullptr, nullptr,
            nullptr, nullptr);                                 // 3 (profiled)
    kScanP1Dinv <<<2*NB + NB, 256>>>();                        // 4
    kScanP2     <<<1, 1024>>>();                               // 5
    kScanP3     <<<2*NB, 256>>>();                             // 6
    k_fill      <<<(EE/4+255)/256, 256>>>(ei);                 // 7
    k_gemm<128,2,1><<<gB, 256, SMEMB>>>(h, nullptr, W_gat, nullptr, nullptr,
            nullptr, nullptr, nullptr, nullptr, g16, h16,
            att_src, att_dst);                                 // 8 (also emits h16)
    kAggGat     <<<2*AGB, 256>>>(b_gat);                       // 9
    k_gemm<256,1,0><<<gB, 256, SMEMB>>>(agg, xgat, Mm, W_fus, b_fus,
            h, gamma, beta, z, nullptr, nullptr,
            nullptr, nullptr);                                 // 10
    k_readout   <<<(NN+31)/32, 1024>>>(W_r1, b_r1, W_r2, b_r2, out);
}

// round 14
// speedup vs baseline: 1.2779x; 1.2779x over previous
#include <cuda_runtime.h>
#include <cuda_fp16.h>
#include <mma.h>
#include <math.h>
#include <stdint.h>
using namespace nvcuda;

#define NN   100000
#define EE   1600000
#define HID  128
#define HEADS 4
#define NEG  0.2f
#define LNEPS 1e-5f
#define NB   391           // (NN+255)/256
#define AGB  12500         // NN/8 warp-per-node blocks

#define ALD 72             // half ld, A tile [64][ALD]
#define BLD 72             // half ld, W tile [128][BLD]
#define CLD 132            // float ld, C stage [64][CLD]
#define SMEMW (64*CLD*4)   // 33792 B (covers 64*ALD*2 + 128*BLD*2 = 27648 too)

// ---------------- device scratch ----------------
__device__ __align__(256) float  g_h   [(size_t)NN*HID];
__device__ __align__(256) __half g_h16 [(size_t)NN*HID];
__device__ __align__(256) __half g_g16 [(size_t)NN*HID];
__device__ __align__(256) float  g_agg [(size_t)NN*HID];
__device__ __align__(256) float  g_xgat[(size_t)NN*HID];
__device__ __align__(256) float  g_z   [(size_t)NN*HID];
__device__ __align__(256) float  g_M   [HID*HID];
__device__ __align__(16)  float  g_asrc[(size_t)NN*HEADS];
__device__ __align__(16)  float  g_adst[(size_t)NN*HEADS];
__device__ float g_dinv[NN];
__device__ int   g_cnt_row[NN];
__device__ int   g_cnt_col[NN];
__device__ int   g_rptr[NN+1];
__device__ int   g_cptr[NN+1];
__device__ int   g_rcur[NN];
__device__ int   g_ccur[NN];
__device__ int   g_csr_rc[EE];
__device__ int   g_csr_cs[EE];
__device__ int   g_part[2*NB];
__device__ int   g_shift;

// ---------------- helpers ----------------
__device__ __forceinline__ float wsum(float x){
    #pragma unroll
    for (int o=16;o;o>>=1) x += __shfl_xor_sync(0xffffffffu, x, o);
    return x;
}
__device__ __forceinline__ int wsumi(int x){
    #pragma unroll
    for (int o=16;o;o>>=1) x += __shfl_xor_sync(0xffffffffu, x, o);
    return x;
}
__device__ __forceinline__ float lrelu(float x){ return x > 0.f ? x : NEG * x; }

typedef unsigned long long ull;
__device__ __forceinline__ ull pack2(float x, float y){
    ull r; asm("mov.b64 %0, {%1,%2};" : "=l"(r) : "f"(x), "f"(y)); return r;
}
__device__ __forceinline__ void unpack2(ull v, float &x, float &y){
    asm("mov.b64 {%0,%1}, %2;" : "=f"(x), "=f"(y) : "l"(v));
}
__device__ __forceinline__ void ffma2(ull &d, ull a, ull b){
    asm("fma.rn.f32x2 %0, %1, %2, %0;" : "+l"(d) : "l"(a), "l"(b));
}
__device__ __forceinline__ void gather_h4(const __half* base, size_t row, int lane,
                                          float w, float4 &acc){
    uint2 u = ((const uint2*)(base + row*HID))[lane];
    float2 f01 = __half22float2(*(const __half2*)&u.x);
    float2 f23 = __half22float2(*(const __half2*)&u.y);
    acc.x = fmaf(w, f01.x, acc.x);
    acc.y = fmaf(w, f01.y, acc.y);
    acc.z = fmaf(w, f23.x, acc.z);
    acc.w = fmaf(w, f23.y, acc.w);
}

// ---------------- init ----------------
__global__ void kInit(const int* ei){
    if (blockIdx.x == 0){
        if (threadIdx.x == 0){
            int acc = 0;
            #pragma unroll 1
            for (int i = 1; i < 128; i += 2) acc |= ei[i];
            g_shift = (acc == 0) ? 1 : 0;
        }
    } else {
        int i = (blockIdx.x-1)*256 + threadIdx.x;
        if (i < NN){ g_cnt_row[i]=0; g_cnt_col[i]=0; }
    }
}

// ---------------- small weight-fold: g_M = Wf1 @ W_e8 ----------------
__global__ void kSmallMM(const float* __restrict__ Wfus, const float* __restrict__ We8){
    int tid = threadIdx.x;
    int half_ = tid >> 7, k = tid & 127;
    int c = blockIdx.x*2 + half_;
    float acc = 0.f;
    #pragma unroll 8
    for (int j = 0; j < 128; j++)
        acc = fmaf(Wfus[c*256 + j], We8[j*128 + k], acc);
    g_M[c*128 + k] = acc;
}

// ---------------- edge loads (x4 vectorized) ----------------
__device__ __forceinline__ void load_edges4(const int* ei, int e0, int sh, int* r, int* c){
    if (sh == 0){
        int4 rr = *(const int4*)(ei + e0);
        int4 cc = *(const int4*)(ei + (size_t)EE + e0);
        r[0]=rr.x; r[1]=rr.y; r[2]=rr.z; r[3]=rr.w;
        c[0]=cc.x; c[1]=cc.y; c[2]=cc.z; c[3]=cc.w;
    } else {
        int4 a = *(const int4*)(ei + 2*(size_t)e0);
        int4 b = *(const int4*)(ei + 2*(size_t)e0 + 4);
        r[0]=a.x; r[1]=a.z; r[2]=b.x; r[3]=b.z;
        int4 d = *(const int4*)(ei + 2*(size_t)EE + 2*(size_t)e0);
        int4 f = *(const int4*)(ei + 2*(size_t)EE + 2*(size_t)e0 + 4);
        c[0]=d.x; c[1]=d.z; c[2]=f.x; c[3]=f.z;
    }
}

__global__ void k_hist(const int* ei){
    int e0 = (blockIdx.x*blockDim.x + threadIdx.x)*4;
    if (e0 >= EE) return;
    int r[4], c[4];
    load_edges4(ei, e0, g_shift, r, c);
    #pragma unroll
    for (int j = 0; j < 4; j++){
        atomicAdd(&g_cnt_row[r[j]], 1);
        atomicAdd(&g_cnt_col[c[j]], 1);
    }
}

__global__ void k_fill(const int* ei){
    int e0 = (blockIdx.x*blockDim.x + threadIdx.x)*4;
    if (e0 >= EE) return;
    int r[4], c[4];
    load_edges4(ei, e0, g_shift, r, c);
    #pragma unroll
    for (int j = 0; j < 4; j++){
        int p = atomicAdd(&g_rcur[r[j]], 1);
        g_csr_rc[p] = c[j];
        int q = atomicAdd(&g_ccur[c[j]], 1);
        g_csr_cs[q] = r[j];
    }
}

// ---------------- scan ----------------
__global__ void kScanP1Dinv(){
    int t = blockIdx.x;
    if (t < 2*NB){
        const int* cnt = (t < NB) ? g_cnt_row : g_cnt_col;
        int i = ((t < NB) ? t : t - NB)*256 + threadIdx.x;
        int v = (i < NN) ? cnt[i] : 0;
        int ws = wsumi(v);
        __shared__ int sums[8];
        int lane = threadIdx.x & 31, warp = threadIdx.x >> 5;
        if (lane == 0) sums[warp] = ws;
        __syncthreads();
        if (threadIdx.x == 0){
            int s = 0;
            #pragma unroll
            for (int w = 0; w < 8; w++) s += sums[w];
            g_part[t] = s;
        }
    } else {
        int i = (t - 2*NB)*256 + threadIdx.x;
        if (i < NN){
            int d = g_cnt_col[i];
            g_dinv[i] = d > 0 ? rsqrtf((float)d) : 0.f;
        }
    }
}

__global__ __launch_bounds__(1024)
void kScanP2(){
    __shared__ int sh[1024];
    int tid = threadIdx.x;
    int half_ = tid >> 9, li = tid & 511;
    int idx = half_ ? NB + li : li;
    int v = (li < NB) ? g_part[idx] : 0;
    sh[tid] = v; __syncthreads();
    #pragma unroll
    for (int off = 1; off < 512; off <<= 1){
        int y = (li >= off) ? sh[tid - off] : 0;
        __syncthreads();
        sh[tid] += y;
        __syncthreads();
    }
    if (li < NB) g_part[idx] = sh[tid] - v;
    if (tid == 0){ g_rptr[NN] = EE; g_cptr[NN] = EE; }
}

__global__ void kScanP3(){
    int t = blockIdx.x;
    int isrow = (t < NB);
    const int* cnt = isrow ? g_cnt_row : g_cnt_col;
    int* ptr = isrow ? g_rptr : g_cptr;
    int* cur = isrow ? g_rcur : g_ccur;
    int i = (isrow ? t : t - NB)*256 + threadIdx.x;
    int v = (i < NN) ? cnt[i] : 0;
    int lane = threadIdx.x & 31, warp = threadIdx.x >> 5;
    int x = v;
    #pragma unroll
    for (int o=1;o<32;o<<=1){
        int y = __shfl_up_sync(0xffffffffu, x, o);
        if (lane >= o) x += y;
    }
    __shared__ int sums[8];
    __shared__ int offs[8];
    if (lane == 31) sums[warp] = x;
    __syncthreads();
    if (threadIdx.x == 0){
        int s = 0;
        #pragma unroll
        for (int w = 0; w < 8; w++){ offs[w] = s; s += sums[w]; }
    }
    __syncthreads();
    int ex = x - v + offs[warp] + g_part[t];
    if (i < NN){ ptr[i] = ex; cur[i] = ex; }
}

// ---------------- WMMA GEMM: C[N,128] = A[N,KTOT] @ W^T via HMMA fp16 ----
// Block 256 thr / 8 warps; warp (wm=warp&3, wn=warp>>2) owns 16x64 tile.
// EPI: 0 plain(+bias), 1 residual+LN+ReLU, 2 plain + attention logits
template<int KTOT, int EPI>
__global__ __launch_bounds__(256)
void k_wgemm(const float* __restrict__ A0, const float* __restrict__ A1,
             const float* __restrict__ W,  const float* __restrict__ W2,
             const float* __restrict__ bias,
             const float* __restrict__ res, const float* __restrict__ gamma,
             const float* __restrict__ beta, float* __restrict__ C,
             __half* __restrict__ C16,
             const float* __restrict__ att_s, const float* __restrict__ att_d)
{
    extern __shared__ char smraw[];
    __half* Ah = (__half*)smraw;                 // [64][ALD]
    __half* Wh = (__half*)(smraw + 64*ALD*2);    // [128][BLD]
    float*  Cs = (float*)smraw;                  // [64][CLD] (phase 2 overlay)

    int tid  = threadIdx.x;
    int row0 = blockIdx.x * 64;
    int lane = tid & 31, warp = tid >> 5;
    int wm = warp & 3, wn = warp >> 2;

    wmma::fragment<wmma::accumulator,16,16,16,float> accf[4];
    #pragma unroll
    for (int j = 0; j < 4; j++) wmma::fill_fragment(accf[j], 0.f);

    const int NCH = KTOT / 64;
    #pragma unroll
    for (int ch = 0; ch < NCH; ch++){
        const float* A = (KTOT == 256 && ch >= 2) ? A1 : A0;
        int acol = (KTOT == 256) ? (ch & 1)*64 : ch*64;
        const float* Wp; int wstride, woff;
        if (KTOT == 256 && ch >= 2){ Wp = W2; wstride = 256; woff = 128 + (ch-2)*64; }
        else                       { Wp = W;  wstride = 128; woff = (ch & 1)*64; }
        for (int idx = tid; idx < 128*64; idx += 256){
            int o = idx >> 6, k = idx & 63;
            Wh[o*BLD + k] = __float2half(Wp[(size_t)o*wstride + woff + k]);
        }
        for (int idx = tid; idx < 64*64; idx += 256){
            int r = idx >> 6, k = idx & 63;
            int gr = row0 + r;
            Ah[r*ALD + k] = __float2half(gr < NN ? A[(size_t)gr*128 + acol + k] : 0.f);
        }
        __syncthreads();

        #pragma unroll
        for (int ks = 0; ks < 64; ks += 16){
            wmma::fragment<wmma::matrix_a,16,16,16,__half,wmma::row_major> af;
            wmma::load_matrix_sync(af, Ah + (wm*16)*ALD + ks, ALD);
            #pragma unroll
            for (int j = 0; j < 4; j++){
                wmma::fragment<wmma::matrix_b,16,16,16,__half,wmma::col_major> bf;
                wmma::load_matrix_sync(bf, Wh + (size_t)(wn*64 + j*16)*BLD + ks, BLD);
                wmma::mma_sync(accf[j], af, bf, accf[j]);
            }
        }
        __syncthreads();
    }

    // stage accumulators (Cs overlays Ah/Wh; all reads done)
    #pragma unroll
    for (int j = 0; j < 4; j++)
        wmma::store_matrix_sync(Cs + (wm*16)*CLD + wn*64 + j*16, accf[j], CLD,
                                wmma::mem_row_major);
    __syncthreads();

    // per-row epilogue: warp handles rows warp*8 .. +8
    int r0 = warp * 8;
    float as_[4], ad_[4];
    if (EPI == 2){
        #pragma unroll
        for (int j = 0; j < 4; j++){ as_[j] = att_s[j*32+lane]; ad_[j] = att_d[j*32+lane]; }
    }
    #pragma unroll
    for (int i = 0; i < 8; i++){
        int gr = row0 + r0 + i;
        if (gr >= NN) continue;
        float v[4];
        #pragma unroll
        for (int j = 0; j < 4; j++){
            float b = bias ? bias[lane + 32*j] : 0.f;
            v[j] = Cs[(r0+i)*CLD + lane + 32*j] + b;
        }
        if (EPI != 1){
            if (C){
                #pragma unroll
                for (int j = 0; j < 4; j++)
                    C[(size_t)gr*128 + lane + 32*j] = v[j];
            }
            if (C16){
                #pragma unroll
                for (int j = 0; j < 4; j++)
                    C16[(size_t)gr*128 + lane + 32*j] = __float2half(v[j]);
            }
            if (EPI == 2){
                #pragma unroll
                for (int j = 0; j < 4; j++){
                    float sj = wsum(v[j]*as_[j]);
                    float dj = wsum(v[j]*ad_[j]);
                    if (lane == 0){
                        g_asrc[(size_t)gr*4+j] = sj;
                        g_adst[(size_t)gr*4+j] = dj;
                    }
                }
            }
        } else {
            #pragma unroll
            for (int j = 0; j < 4; j++)
                v[j] += res[(size_t)gr*128 + lane + 32*j];
            float s = v[0]+v[1]+v[2]+v[3];
            float mu = wsum(s) * (1.f/128.f);
            float q = 0.f;
            #pragma unroll
            for (int j = 0; j < 4; j++){ float d = v[j]-mu; q = fmaf(d,d,q); }
            float sc = rsqrtf(wsum(q) * (1.f/128.f) + LNEPS);
            #pragma unroll
            for (int j = 0; j < 4; j++){
                int c = lane + 32*j;
                float o = (v[j]-mu)*sc*gamma[c] + beta[c];
                C[(size_t)gr*128 + c] = fmaxf(o, 0.f);
            }
        }
    }
}

// ---------------- E8 aggregation body (fp16 gathers) ----------------
__device__ __forceinline__ void e8agg_body(int bid){
    int w = bid*8 + (threadIdx.x >> 5);
    if (w >= NN) return;
    int lane = threadIdx.x & 31;
    int s = g_rptr[w], e = g_rptr[w+1];
    float4 acc = make_float4(0.f,0.f,0.f,0.f);
    #pragma unroll 2
    for (int i = s; i < e; i++){
        int c = g_csr_rc[i];
        gather_h4(g_h16, (size_t)c, lane, g_dinv[c], acc);
    }
    float du = g_dinv[w];
    float4 o = make_float4(du*acc.x, du*acc.y, du*acc.z, du*acc.w);
    ((float4*)(g_agg + (size_t)w*128))[lane] = o;
}

// ---------------- GAT body (online softmax, fp16 feature gathers) ----------
__device__ __forceinline__ void gat_body(int bid, const float* __restrict__ bgat){
    int v = bid*8 + (threadIdx.x >> 5);
    if (v >= NN) return;
    int lane = threadIdx.x & 31;
    int s = g_cptr[v], e = g_cptr[v+1];

    float4 ad = ((const float4*)g_adst)[v];
    float4 asl = ((const float4*)g_asrc)[v];
    float es[4] = { lrelu(asl.x + ad.x), lrelu(asl.y + ad.y),
                    lrelu(asl.z + ad.z), lrelu(asl.w + ad.w) };

    float m[4]  = { es[0], es[1], es[2], es[3] };
    float sm[4] = { 0.f, 0.f, 0.f, 0.f };
    for (int i = s + lane; i < e; i += 32){
        int u = g_csr_cs[i];
        float4 a = ((const float4*)g_asrc)[u];
        float ev[4] = { lrelu(a.x + ad.x), lrelu(a.y + ad.y),
                        lrelu(a.z + ad.z), lrelu(a.w + ad.w) };
        #pragma unroll
        for (int j = 0; j < 4; j++){
            float mn = fmaxf(m[j], ev[j]);
            sm[j] = sm[j]*__expf(m[j]-mn) + __expf(ev[j]-mn);
            m[j] = mn;
        }
    }
    #pragma unroll
    for (int j = 0; j < 4; j++){
        float mj = m[j], sj = sm[j];
        #pragma unroll
        for (int o = 16; o; o >>= 1){
            float m2 = __shfl_xor_sync(0xffffffffu, mj, o);
            float s2 = __shfl_xor_sync(0xffffffffu, sj, o);
            float mn = fmaxf(mj, m2);
            sj = sj*__expf(mj-mn) + s2*__expf(m2-mn);
            mj = mn;
        }
        sj += __expf(es[j]-mj);
        m[j] = mj;
        sm[j] = 1.f/(sj + 1e-16f);
    }

    int hidx = lane >> 3;
    float adh = (hidx==0)?ad.x : (hidx==1)?ad.y : (hidx==2)?ad.z : ad.w;
    float mh  = m[hidx];
    float ih  = sm[hidx];
    float esh = es[hidx];

    float4 acc = make_float4(0.f,0.f,0.f,0.f);
    #pragma unroll 2
    for (int i = s; i < e; i++){
        int u = g_csr_cs[i];
        float a = g_asrc[(size_t)u*4 + hidx];
        float alpha = __expf(lrelu(a + adh) - mh) * ih;
        gather_h4(g_g16, (size_t)u, lane, alpha, acc);
    }
    {
        float alpha = __expf(esh - mh) * ih;
        gather_h4(g_g16, (size_t)v, lane, alpha, acc);
    }
    float4 b = ((const float4*)bgat)[lane];
    acc.x += b.x; acc.y += b.y; acc.z += b.z; acc.w += b.w;
    ((float4*)(g_xgat + (size_t)v*128))[lane] = acc;
}

__global__ __launch_bounds__(256)
void kAggGat(const float* __restrict__ bgat){
    if (blockIdx.x < AGB) gat_body(blockIdx.x, bgat);
    else                  e8agg_body(blockIdx.x - AGB);
}

// ---------------- fused readout ----------------
__global__ __launch_bounds__(1024)
void k_readout(const float* __restrict__ Wr1, const float* __restrict__ br1,
               const float* __restrict__ Wr2, const float* __restrict__ br2,
               float* __restrict__ out)
{
    __shared__ ull Ws2[128*32];
    int tid = threadIdx.x;
    for (int idx = tid; idx < 128*32; idx += 1024){
        int k = idx >> 5, o = idx & 31;
        Ws2[idx] = pack2(Wr1[(size_t)o*128 + k], Wr1[(size_t)(o+32)*128 + k]);
    }
    __syncthreads();
    int warp = tid >> 5, lane = tid & 31;
    int node = blockIdx.x*32 + warp;
    if (node >= NN) return;

    float4 zv = ((const float4*)(g_z + (size_t)node*128))[lane];
    ull acc = pack2(br1[lane], br1[lane+32]);
    #pragma unroll 8
    for (int kb = 0; kb < 32; kb++){
        float zx = __shfl_sync(0xffffffffu, zv.x, kb);
        float zy = __shfl_sync(0xffffffffu, zv.y, kb);
        float zz = __shfl_sync(0xffffffffu, zv.z, kb);
        float zw = __shfl_sync(0xffffffffu, zv.w, kb);
        int k = kb*4;
        ffma2(acc, pack2(zx,zx), Ws2[(k+0)*32+lane]);
        ffma2(acc, pack2(zy,zy), Ws2[(k+1)*32+lane]);
        ffma2(acc, pack2(zz,zz), Ws2[(k+2)*32+lane]);
        ffma2(acc, pack2(zw,zw), Ws2[(k+3)*32+lane]);
    }
    float a0, a1; unpack2(acc, a0, a1);
    float r0 = fmaxf(a0, 0.f);
    float r1 = fmaxf(a1, 0.f);
    float p = fmaf(r0, Wr2[lane], r1 * Wr2[lane+32]);
    p = wsum(p);
    if (lane == 0){
        float xv = p + br2[0];
        out[node] = 1.f / (1.f + __expf(-xv));
    }
}

// ---------------- host ----------------
extern "C" void kernel_launch(void* const* d_in, const int* in_sizes, int n_in,
                              void* d_out, int out_size)
{
    const float* x       = (const float*)d_in[0];
    const int*   ei      = (const int*)  d_in[1];
    const float* W_emb   = (const float*)d_in[2];
    const float* b_emb   = (const float*)d_in[3];
    const float* W_e8    = (const float*)d_in[4];
    const float* W_gat   = (const float*)d_in[5];
    const float* att_src = (const float*)d_in[6];
    const float* att_dst = (const float*)d_in[7];
    const float* b_gat   = (const float*)d_in[8];
    const float* W_fus   = (const float*)d_in[9];
    const float* b_fus   = (const float*)d_in[10];
    const float* gamma   = (const float*)d_in[11];
    const float* beta    = (const float*)d_in[12];
    const float* W_r1    = (const float*)d_in[13];
    const float* b_r1    = (const float*)d_in[14];
    const float* W_r2    = (const float*)d_in[15];
    const float* b_r2    = (const float*)d_in[16];
    float* out = (float*)d_out;

    float *h, *agg, *xgat, *z, *Mm;
    __half *h16, *g16;
    cudaGetSymbolAddress((void**)&h,    g_h);
    cudaGetSymbolAddress((void**)&h16,  g_h16);
    cudaGetSymbolAddress((void**)&g16,  g_g16);
    cudaGetSymbolAddress((void**)&agg,  g_agg);
    cudaGetSymbolAddress((void**)&xgat, g_xgat);
    cudaGetSymbolAddress((void**)&z,    g_z);
    cudaGetSymbolAddress((void**)&Mm,   g_M);

    cudaFuncSetAttribute((void*)k_wgemm<128,0>, cudaFuncAttributeMaxDynamicSharedMemorySize, SMEMW);
    cudaFuncSetAttribute((void*)k_wgemm<128,2>, cudaFuncAttributeMaxDynamicSharedMemorySize, SMEMW);
    cudaFuncSetAttribute((void*)k_wgemm<256,1>, cudaFuncAttributeMaxDynamicSharedMemorySize, SMEMW);

    const int gB = (NN + 63) / 64;

    kInit       <<<1 + NB, 256>>>(ei);                         // 0
    k_hist      <<<(EE/4+255)/256, 256>>>(ei);                 // 1
    kSmallMM    <<<64, 256>>>(W_fus, W_e8);                    // 2
    k_wgemm<128,0><<<gB, 256, SMEMW>>>(x, nullptr, W_emb, nullptr, b_emb,
            nullptr, nullptr, nullptr, h, h16, nullptr, nullptr); // 3 (profiled)
    kScanP1Dinv <<<2*NB + NB, 256>>>();                        // 4
    kScanP2     <<<1, 1024>>>();                               // 5
    kScanP3     <<<2*NB, 256>>>();                             // 6
    k_fill      <<<(EE/4+255)/256, 256>>>(ei);                 // 7
    k_wgemm<128,2><<<gB, 256, SMEMW>>>(h, nullptr, W_gat, nullptr, nullptr,
            nullptr, nullptr, nullptr, nullptr, g16, att_src, att_dst); // 8
    kAggGat     <<<2*AGB, 256>>>(b_gat);                       // 9
    k_wgemm<256,1><<<gB, 256, SMEMW>>>(agg, xgat, Mm, W_fus, b_fus,
            h, gamma, beta, z, nullptr, nullptr, nullptr);     // 10
    k_readout   <<<(NN+31)/32, 1024>>>(W_r1, b_r1, W_r2, b_r2, out);
}

// round 15
// speedup vs baseline: 1.4062x; 1.1004x over previous
#include <cuda_runtime.h>
#include <cuda_fp16.h>
#include <mma.h>
#include <math.h>
#include <stdint.h>
using namespace nvcuda;

#define NN   100000
#define EE   1600000
#define HID  128
#define HEADS 4
#define NEG  0.2f
#define LNEPS 1e-5f
#define NB   391           // (NN+255)/256
#define AGB  12500         // NN/8 warp-per-node blocks

#define ALD 72             // half ld, A tile [64][ALD]
#define BLD 72             // half ld, W tile [128][BLD]
#define CLD 132            // float ld, C stage [64][CLD]
#define SMEMW (64*CLD*4)               // 33792 B (plain wgemm)
#define SMEMF (64*CLD*4 + 128*32*8)    // 66560 B (fusion + readout pairs)

// ---------------- device scratch ----------------
__device__ __align__(256) float  g_h   [(size_t)NN*HID];
__device__ __align__(256) __half g_h16 [(size_t)NN*HID];
__device__ __align__(256) __half g_g16 [(size_t)NN*HID];
__device__ __align__(256) float  g_agg [(size_t)NN*HID];
__device__ __align__(256) float  g_xgat[(size_t)NN*HID];
__device__ __align__(256) float  g_M   [HID*HID];
__device__ __align__(16)  float  g_asrc[(size_t)NN*HEADS];
__device__ __align__(16)  float  g_adst[(size_t)NN*HEADS];
__device__ float g_dinv[NN];
__device__ int   g_cnt_row[NN];
__device__ int   g_cnt_col[NN];
__device__ int   g_rptr[NN+1];
__device__ int   g_cptr[NN+1];
__device__ int   g_rcur[NN];
__device__ int   g_ccur[NN];
__device__ int   g_csr_rc[EE];
__device__ int   g_csr_cs[EE];
__device__ int   g_part[2*NB];
__device__ int   g_shift;

// ---------------- helpers ----------------
__device__ __forceinline__ float wsum(float x){
    #pragma unroll
    for (int o=16;o;o>>=1) x += __shfl_xor_sync(0xffffffffu, x, o);
    return x;
}
__device__ __forceinline__ int wsumi(int x){
    #pragma unroll
    for (int o=16;o;o>>=1) x += __shfl_xor_sync(0xffffffffu, x, o);
    return x;
}
__device__ __forceinline__ float lrelu(float x){ return x > 0.f ? x : NEG * x; }

typedef unsigned long long ull;
__device__ __forceinline__ ull pack2(float x, float y){
    ull r; asm("mov.b64 %0, {%1,%2};" : "=l"(r) : "f"(x), "f"(y)); return r;
}
__device__ __forceinline__ void unpack2(ull v, float &x, float &y){
    asm("mov.b64 {%0,%1}, %2;" : "=f"(x), "=f"(y) : "l"(v));
}
__device__ __forceinline__ void ffma2(ull &d, ull a, ull b){
    asm("fma.rn.f32x2 %0, %1, %2, %0;" : "+l"(d) : "l"(a), "l"(b));
}
__device__ __forceinline__ void gather_h4(const __half* base, size_t row, int lane,
                                          float w, float4 &acc){
    uint2 u = ((const uint2*)(base + row*HID))[lane];
    float2 f01 = __half22float2(*(const __half2*)&u.x);
    float2 f23 = __half22float2(*(const __half2*)&u.y);
    acc.x = fmaf(w, f01.x, acc.x);
    acc.y = fmaf(w, f01.y, acc.y);
    acc.z = fmaf(w, f23.x, acc.z);
    acc.w = fmaf(w, f23.y, acc.w);
}

// ---------------- init ----------------
__global__ void kInit(const int* ei){
    if (blockIdx.x == 0){
        if (threadIdx.x == 0){
            int acc = 0;
            #pragma unroll 1
            for (int i = 1; i < 128; i += 2) acc |= ei[i];
            g_shift = (acc == 0) ? 1 : 0;
        }
    } else {
        int i = (blockIdx.x-1)*256 + threadIdx.x;
        if (i < NN){ g_cnt_row[i]=0; g_cnt_col[i]=0; }
    }
}

// ---------------- small weight-fold: g_M = Wf1 @ W_e8 ----------------
__global__ void kSmallMM(const float* __restrict__ Wfus, const float* __restrict__ We8){
    int tid = threadIdx.x;
    int half_ = tid >> 7, k = tid & 127;
    int c = blockIdx.x*2 + half_;
    float acc = 0.f;
    #pragma unroll 8
    for (int j = 0; j < 128; j++)
        acc = fmaf(Wfus[c*256 + j], We8[j*128 + k], acc);
    g_M[c*128 + k] = acc;
}

// ---------------- edge loads (x4 vectorized) ----------------
__device__ __forceinline__ void load_edges4(const int* ei, int e0, int sh, int* r, int* c){
    if (sh == 0){
        int4 rr = *(const int4*)(ei + e0);
        int4 cc = *(const int4*)(ei + (size_t)EE + e0);
        r[0]=rr.x; r[1]=rr.y; r[2]=rr.z; r[3]=rr.w;
        c[0]=cc.x; c[1]=cc.y; c[2]=cc.z; c[3]=cc.w;
    } else {
        int4 a = *(const int4*)(ei + 2*(size_t)e0);
        int4 b = *(const int4*)(ei + 2*(size_t)e0 + 4);
        r[0]=a.x; r[1]=a.z; r[2]=b.x; r[3]=b.z;
        int4 d = *(const int4*)(ei + 2*(size_t)EE + 2*(size_t)e0);
        int4 f = *(const int4*)(ei + 2*(size_t)EE + 2*(size_t)e0 + 4);
        c[0]=d.x; c[1]=d.z; c[2]=f.x; c[3]=f.z;
    }
}

__global__ void k_hist(const int* ei){
    int e0 = (blockIdx.x*blockDim.x + threadIdx.x)*4;
    if (e0 >= EE) return;
    int r[4], c[4];
    load_edges4(ei, e0, g_shift, r, c);
    #pragma unroll
    for (int j = 0; j < 4; j++){
        atomicAdd(&g_cnt_row[r[j]], 1);
        atomicAdd(&g_cnt_col[c[j]], 1);
    }
}

__global__ void k_fill(const int* ei){
    int e0 = (blockIdx.x*blockDim.x + threadIdx.x)*4;
    if (e0 >= EE) return;
    int r[4], c[4];
    load_edges4(ei, e0, g_shift, r, c);
    #pragma unroll
    for (int j = 0; j < 4; j++){
        int p = atomicAdd(&g_rcur[r[j]], 1);
        g_csr_rc[p] = c[j];
        int q = atomicAdd(&g_ccur[c[j]], 1);
        g_csr_cs[q] = r[j];
    }
}

// ---------------- scan ----------------
__global__ void kScanP1Dinv(){
    int t = blockIdx.x;
    if (t < 2*NB){
        const int* cnt = (t < NB) ? g_cnt_row : g_cnt_col;
        int i = ((t < NB) ? t : t - NB)*256 + threadIdx.x;
        int v = (i < NN) ? cnt[i] : 0;
        int ws = wsumi(v);
        __shared__ int sums[8];
        int lane = threadIdx.x & 31, warp = threadIdx.x >> 5;
        if (lane == 0) sums[warp] = ws;
        __syncthreads();
        if (threadIdx.x == 0){
            int s = 0;
            #pragma unroll
            for (int w = 0; w < 8; w++) s += sums[w];
            g_part[t] = s;
        }
    } else {
        int i = (t - 2*NB)*256 + threadIdx.x;
        if (i < NN){
            int d = g_cnt_col[i];
            g_dinv[i] = d > 0 ? rsqrtf((float)d) : 0.f;
        }
    }
}

__global__ __launch_bounds__(1024)
void kScanP2(){
    __shared__ int sh[1024];
    int tid = threadIdx.x;
    int half_ = tid >> 9, li = tid & 511;
    int idx = half_ ? NB + li : li;
    int v = (li < NB) ? g_part[idx] : 0;
    sh[tid] = v; __syncthreads();
    #pragma unroll
    for (int off = 1; off < 512; off <<= 1){
        int y = (li >= off) ? sh[tid - off] : 0;
        __syncthreads();
        sh[tid] += y;
        __syncthreads();
    }
    if (li < NB) g_part[idx] = sh[tid] - v;
    if (tid == 0){ g_rptr[NN] = EE; g_cptr[NN] = EE; }
}

__global__ void kScanP3(){
    int t = blockIdx.x;
    int isrow = (t < NB);
    const int* cnt = isrow ? g_cnt_row : g_cnt_col;
    int* ptr = isrow ? g_rptr : g_cptr;
    int* cur = isrow ? g_rcur : g_ccur;
    int i = (isrow ? t : t - NB)*256 + threadIdx.x;
    int v = (i < NN) ? cnt[i] : 0;
    int lane = threadIdx.x & 31, warp = threadIdx.x >> 5;
    int x = v;
    #pragma unroll
    for (int o=1;o<32;o<<=1){
        int y = __shfl_up_sync(0xffffffffu, x, o);
        if (lane >= o) x += y;
    }
    __shared__ int sums[8];
    __shared__ int offs[8];
    if (lane == 31) sums[warp] = x;
    __syncthreads();
    if (threadIdx.x == 0){
        int s = 0;
        #pragma unroll
        for (int w = 0; w < 8; w++){ offs[w] = s; s += sums[w]; }
    }
    __syncthreads();
    int ex = x - v + offs[warp] + g_part[t];
    if (i < NN){ ptr[i] = ex; cur[i] = ex; }
}

// ---------------- WMMA GEMM (plain / att-logit epilogues) ----
// EPI: 0 plain(+bias), 2 plain + attention logits
template<int EPI>
__global__ __launch_bounds__(256)
void k_wgemm(const float* __restrict__ A0,
             const float* __restrict__ W,
             const float* __restrict__ bias,
             float* __restrict__ C, __half* __restrict__ C16,
             const float* __restrict__ att_s, const float* __restrict__ att_d)
{
    extern __shared__ char smraw[];
    __half* Ah = (__half*)smraw;                 // [64][ALD]
    __half* Wh = (__half*)(smraw + 64*ALD*2);    // [128][BLD]
    float*  Cs = (float*)smraw;                  // [64][CLD] (phase 2 overlay)

    int tid  = threadIdx.x;
    int row0 = blockIdx.x * 64;
    int lane = tid & 31, warp = tid >> 5;
    int wm = warp & 3, wn = warp >> 2;

    wmma::fragment<wmma::accumulator,16,16,16,float> accf[4];
    #pragma unroll
    for (int j = 0; j < 4; j++) wmma::fill_fragment(accf[j], 0.f);

    #pragma unroll
    for (int ch = 0; ch < 2; ch++){
        for (int idx = tid; idx < 128*64; idx += 256){
            int o = idx >> 6, k = idx & 63;
            Wh[o*BLD + k] = __float2half(W[(size_t)o*128 + ch*64 + k]);
        }
        for (int idx = tid; idx < 64*64; idx += 256){
            int r = idx >> 6, k = idx & 63;
            int gr = row0 + r;
            Ah[r*ALD + k] = __float2half(gr < NN ? A0[(size_t)gr*128 + ch*64 + k] : 0.f);
        }
        __syncthreads();
        #pragma unroll
        for (int ks = 0; ks < 64; ks += 16){
            wmma::fragment<wmma::matrix_a,16,16,16,__half,wmma::row_major> af;
            wmma::load_matrix_sync(af, Ah + (wm*16)*ALD + ks, ALD);
            #pragma unroll
            for (int j = 0; j < 4; j++){
                wmma::fragment<wmma::matrix_b,16,16,16,__half,wmma::col_major> bf;
                wmma::load_matrix_sync(bf, Wh + (size_t)(wn*64 + j*16)*BLD + ks, BLD);
                wmma::mma_sync(accf[j], af, bf, accf[j]);
            }
        }
        __syncthreads();
    }

    #pragma unroll
    for (int j = 0; j < 4; j++)
        wmma::store_matrix_sync(Cs + (wm*16)*CLD + wn*64 + j*16, accf[j], CLD,
                                wmma::mem_row_major);
    __syncthreads();

    int r0 = warp * 8;
    float as_[4], ad_[4];
    if (EPI == 2){
        #pragma unroll
        for (int j = 0; j < 4; j++){ as_[j] = att_s[j*32+lane]; ad_[j] = att_d[j*32+lane]; }
    }
    #pragma unroll
    for (int i = 0; i < 8; i++){
        int gr = row0 + r0 + i;
        if (gr >= NN) continue;
        float v[4];
        #pragma unroll
        for (int j = 0; j < 4; j++){
            float b = bias ? bias[lane + 32*j] : 0.f;
            v[j] = Cs[(r0+i)*CLD + lane + 32*j] + b;
        }
        if (C){
            #pragma unroll
            for (int j = 0; j < 4; j++)
                C[(size_t)gr*128 + lane + 32*j] = v[j];
        }
        if (C16){
            #pragma unroll
            for (int j = 0; j < 4; j++)
                C16[(size_t)gr*128 + lane + 32*j] = __float2half(v[j]);
        }
        if (EPI == 2){
            #pragma unroll
            for (int j = 0; j < 4; j++){
                float sj = wsum(v[j]*as_[j]);
                float dj = wsum(v[j]*ad_[j]);
                if (lane == 0){
                    g_asrc[(size_t)gr*4+j] = sj;
                    g_adst[(size_t)gr*4+j] = dj;
                }
            }
        }
    }
}

// ---------------- fusion GEMM (K=256) + residual + LN + ReLU + READOUT ----
__global__ __launch_bounds__(256)
void kFusGemm(const float* __restrict__ A0, const float* __restrict__ A1,
              const float* __restrict__ Wm, const float* __restrict__ Wfus,
              const float* __restrict__ bias,
              const float* __restrict__ res, const float* __restrict__ gamma,
              const float* __restrict__ beta,
              const float* __restrict__ Wr1, const float* __restrict__ br1,
              const float* __restrict__ Wr2, const float* __restrict__ br2,
              float* __restrict__ out)
{
    extern __shared__ char smraw[];
    __half* Ah = (__half*)smraw;                    // [64][ALD]
    __half* Wh = (__half*)(smraw + 64*ALD*2);       // [128][BLD]   (ends 27648)
    float*  Cs = (float*)smraw;                     // [64][CLD]    (phase-2 overlay, 33792)
    ull*    Ws2 = (ull*)(smraw + 64*CLD*4);         // [128*32] readout pairs (32768)

    int tid  = threadIdx.x;
    int row0 = blockIdx.x * 64;
    int lane = tid & 31, warp = tid >> 5;
    int wm = warp & 3, wn = warp >> 2;

    // stage readout weight pairs once (disjoint region)
    for (int idx = tid; idx < 128*32; idx += 256){
        int k = idx >> 5, o = idx & 31;
        Ws2[idx] = pack2(Wr1[(size_t)o*128 + k], Wr1[(size_t)(o+32)*128 + k]);
    }

    wmma::fragment<wmma::accumulator,16,16,16,float> accf[4];
    #pragma unroll
    for (int j = 0; j < 4; j++) wmma::fill_fragment(accf[j], 0.f);

    #pragma unroll
    for (int ch = 0; ch < 4; ch++){
        const float* A = (ch >= 2) ? A1 : A0;
        int acol = (ch & 1)*64;
        const float* Wp; int wstride, woff;
        if (ch >= 2){ Wp = Wfus; wstride = 256; woff = 128 + (ch-2)*64; }
        else        { Wp = Wm;   wstride = 128; woff = (ch & 1)*64; }
        for (int idx = tid; idx < 128*64; idx += 256){
            int o = idx >> 6, k = idx & 63;
            Wh[o*BLD + k] = __float2half(Wp[(size_t)o*wstride + woff + k]);
        }
        for (int idx = tid; idx < 64*64; idx += 256){
            int r = idx >> 6, k = idx & 63;
            int gr = row0 + r;
            Ah[r*ALD + k] = __float2half(gr < NN ? A[(size_t)gr*128 + acol + k] : 0.f);
        }
        __syncthreads();
        #pragma unroll
        for (int ks = 0; ks < 64; ks += 16){
            wmma::fragment<wmma::matrix_a,16,16,16,__half,wmma::row_major> af;
            wmma::load_matrix_sync(af, Ah + (wm*16)*ALD + ks, ALD);
            #pragma unroll
            for (int j = 0; j < 4; j++){
                wmma::fragment<wmma::matrix_b,16,16,16,__half,wmma::col_major> bf;
                wmma::load_matrix_sync(bf, Wh + (size_t)(wn*64 + j*16)*BLD + ks, BLD);
                wmma::mma_sync(accf[j], af, bf, accf[j]);
            }
        }
        __syncthreads();
    }

    #pragma unroll
    for (int j = 0; j < 4; j++)
        wmma::store_matrix_sync(Cs + (wm*16)*CLD + wn*64 + j*16, accf[j], CLD,
                                wmma::mem_row_major);
    __syncthreads();

    int r0 = warp * 8;
    float w2a = Wr2[lane], w2b = Wr2[lane+32];
    float b2  = br2[0];
    ull   rb  = pack2(br1[lane], br1[lane+32]);

    #pragma unroll
    for (int i = 0; i < 8; i++){
        int gr = row0 + r0 + i;
        if (gr >= NN) continue;
        float v[4];
        #pragma unroll
        for (int j = 0; j < 4; j++)
            v[j] = Cs[(r0+i)*CLD + lane + 32*j] + bias[lane + 32*j]
                 + res[(size_t)gr*128 + lane + 32*j];
        float s = v[0]+v[1]+v[2]+v[3];
        float mu = wsum(s) * (1.f/128.f);
        float q = 0.f;
        #pragma unroll
        for (int j = 0; j < 4; j++){ float d = v[j]-mu; q = fmaf(d,d,q); }
        float sc = rsqrtf(wsum(q) * (1.f/128.f) + LNEPS);
        #pragma unroll
        for (int j = 0; j < 4; j++){
            int c = lane + 32*j;
            v[j] = fmaxf((v[j]-mu)*sc*gamma[c] + beta[c], 0.f);
        }
        // readout: lane holds z dims {l, l+32, l+64, l+96}
        ull racc = rb;
        #pragma unroll 4
        for (int kb = 0; kb < 32; kb++){
            float z0 = __shfl_sync(0xffffffffu, v[0], kb);
            float z1 = __shfl_sync(0xffffffffu, v[1], kb);
            float z2 = __shfl_sync(0xffffffffu, v[2], kb);
            float z3 = __shfl_sync(0xffffffffu, v[3], kb);
            ffma2(racc, pack2(z0,z0), Ws2[(kb     )*32 + lane]);
            ffma2(racc, pack2(z1,z1), Ws2[(kb + 32)*32 + lane]);
            ffma2(racc, pack2(z2,z2), Ws2[(kb + 64)*32 + lane]);
            ffma2(racc, pack2(z3,z3), Ws2[(kb + 96)*32 + lane]);
        }
        float a0, a1; unpack2(racc, a0, a1);
        float pr = fmaf(fmaxf(a0, 0.f), w2a, fmaxf(a1, 0.f) * w2b);
        pr = wsum(pr);
        if (lane == 0)
            out[gr] = 1.f / (1.f + __expf(-(pr + b2)));
    }
}

// ---------------- E8 aggregation body (fp16 gathers) ----------------
__device__ __forceinline__ void e8agg_body(int bid){
    int w = bid*8 + (threadIdx.x >> 5);
    if (w >= NN) return;
    int lane = threadIdx.x & 31;
    int s = g_rptr[w], e = g_rptr[w+1];
    float4 acc = make_float4(0.f,0.f,0.f,0.f);
    #pragma unroll 2
    for (int i = s; i < e; i++){
        int c = g_csr_rc[i];
        gather_h4(g_h16, (size_t)c, lane, g_dinv[c], acc);
    }
    float du = g_dinv[w];
    float4 o = make_float4(du*acc.x, du*acc.y, du*acc.z, du*acc.w);
    ((float4*)(g_agg + (size_t)w*128))[lane] = o;
}

// ---------------- GAT body (online softmax, fp16 feature gathers) ----------
__device__ __forceinline__ void gat_body(int bid, const float* __restrict__ bgat){
    int v = bid*8 + (threadIdx.x >> 5);
    if (v >= NN) return;
    int lane = threadIdx.x & 31;
    int s = g_cptr[v], e = g_cptr[v+1];

    float4 ad = ((const float4*)g_adst)[v];
    float4 asl = ((const float4*)g_asrc)[v];
    float es[4] = { lrelu(asl.x + ad.x), lrelu(asl.y + ad.y),
                    lrelu(asl.z + ad.z), lrelu(asl.w + ad.w) };

    float m[4]  = { es[0], es[1], es[2], es[3] };
    float sm[4] = { 0.f, 0.f, 0.f, 0.f };
    for (int i = s + lane; i < e; i += 32){
        int u = g_csr_cs[i];
        float4 a = ((const float4*)g_asrc)[u];
        float ev[4] = { lrelu(a.x + ad.x), lrelu(a.y + ad.y),
                        lrelu(a.z + ad.z), lrelu(a.w + ad.w) };
        #pragma unroll
        for (int j = 0; j < 4; j++){
            float mn = fmaxf(m[j], ev[j]);
            sm[j] = sm[j]*__expf(m[j]-mn) + __expf(ev[j]-mn);
            m[j] = mn;
        }
    }
    #pragma unroll
    for (int j = 0; j < 4; j++){
        float mj = m[j], sj = sm[j];
        #pragma unroll
        for (int o = 16; o; o >>= 1){
            float m2 = __shfl_xor_sync(0xffffffffu, mj, o);
            float s2 = __shfl_xor_sync(0xffffffffu, sj, o);
            float mn = fmaxf(mj, m2);
            sj = sj*__expf(mj-mn) + s2*__expf(m2-mn);
            mj = mn;
        }
        sj += __expf(es[j]-mj);
        m[j] = mj;
        sm[j] = 1.f/(sj + 1e-16f);
    }

    int hidx = lane >> 3;
    float adh = (hidx==0)?ad.x : (hidx==1)?ad.y : (hidx==2)?ad.z : ad.w;
    float mh  = m[hidx];
    float ih  = sm[hidx];
    float esh = es[hidx];

    float4 acc = make_float4(0.f,0.f,0.f,0.f);
    #pragma unroll 2
    for (int i = s; i < e; i++){
        int u = g_csr_cs[i];
        float a = g_asrc[(size_t)u*4 + hidx];
        float alpha = __expf(lrelu(a + adh) - mh) * ih;
        gather_h4(g_g16, (size_t)u, lane, alpha, acc);
    }
    {
        float alpha = __expf(esh - mh) * ih;
        gather_h4(g_g16, (size_t)v, lane, alpha, acc);
    }
    float4 b = ((const float4*)bgat)[lane];
    acc.x += b.x; acc.y += b.y; acc.z += b.z; acc.w += b.w;
    ((float4*)(g_xgat + (size_t)v*128))[lane] = acc;
}

__global__ __launch_bounds__(256)
void kAggGat(const float* __restrict__ bgat){
    if (blockIdx.x < AGB) gat_body(blockIdx.x, bgat);
    else                  e8agg_body(blockIdx.x - AGB);
}

// ---------------- host ----------------
extern "C" void kernel_launch(void* const* d_in, const int* in_sizes, int n_in,
                              void* d_out, int out_size)
{
    const float* x       = (const float*)d_in[0];
    const int*   ei      = (const int*)  d_in[1];
    const float* W_emb   = (const float*)d_in[2];
    const float* b_emb   = (const float*)d_in[3];
    const float* W_e8    = (const float*)d_in[4];
    const float* W_gat   = (const float*)d_in[5];
    const float* att_src = (const float*)d_in[6];
    const float* att_dst = (const float*)d_in[7];
    const float* b_gat   = (const float*)d_in[8];
    const float* W_fus   = (const float*)d_in[9];
    const float* b_fus   = (const float*)d_in[10];
    const float* gamma   = (const float*)d_in[11];
    const float* beta    = (const float*)d_in[12];
    const float* W_r1    = (const float*)d_in[13];
    const float* b_r1    = (const float*)d_in[14];
    const float* W_r2    = (const float*)d_in[15];
    const float* b_r2    = (const float*)d_in[16];
    float* out = (float*)d_out;

    float *h, *agg, *xgat, *Mm;
    __half *h16, *g16;
    cudaGetSymbolAddress((void**)&h,    g_h);
    cudaGetSymbolAddress((void**)&h16,  g_h16);
    cudaGetSymbolAddress((void**)&g16,  g_g16);
    cudaGetSymbolAddress((void**)&agg,  g_agg);
    cudaGetSymbolAddress((void**)&xgat, g_xgat);
    cudaGetSymbolAddress((void**)&Mm,   g_M);

    cudaFuncSetAttribute((void*)k_wgemm<0>, cudaFuncAttributeMaxDynamicSharedMemorySize, SMEMW);
    cudaFuncSetAttribute((void*)k_wgemm<2>, cudaFuncAttributeMaxDynamicSharedMemorySize, SMEMW);
    cudaFuncSetAttribute((void*)kFusGemm,   cudaFuncAttributeMaxDynamicSharedMemorySize, SMEMF);

    const int gB = (NN + 63) / 64;

    kInit       <<<1 + NB, 256>>>(ei);                         // 0
    k_hist      <<<(EE/4+255)/256, 256>>>(ei);                 // 1
    kSmallMM    <<<64, 256>>>(W_fus, W_e8);                    // 2
    k_wgemm<0>  <<<gB, 256, SMEMW>>>(x, W_emb, b_emb,
            h, h16, nullptr, nullptr);                         // 3 (profiled)
    kScanP1Dinv <<<2*NB + NB, 256>>>();                        // 4
    kScanP2     <<<1, 1024>>>();                               // 5
    kScanP3     <<<2*NB, 256>>>();                             // 6
    k_fill      <<<(EE/4+255)/256, 256>>>(ei);                 // 7
    k_wgemm<2>  <<<gB, 256, SMEMW>>>(h, W_gat, nullptr,
            nullptr, g16, att_src, att_dst);                   // 8
    kAggGat     <<<2*AGB, 256>>>(b_gat);                       // 9
    kFusGemm    <<<gB, 256, SMEMF>>>(agg, xgat, Mm, W_fus, b_fus,
            h, gamma, beta, W_r1, b_r1, W_r2, b_r2, out);      // 10
}

// round 16
// speedup vs baseline: 1.4285x; 1.0158x over previous
#include <cuda_runtime.h>
#include <cuda_fp16.h>
#include <mma.h>
#include <math.h>
#include <stdint.h>
using namespace nvcuda;

#define NN   100000
#define EE   1600000
#define HID  128
#define HEADS 4
#define NEG  0.2f
#define LNEPS 1e-5f
#define NB   391           // (NN+255)/256
#define AGB  12500         // NN/8 warp-per-node blocks

#define ALD 72             // half ld, A tile [64][ALD]
#define BLD 72             // half ld, W tile [128][BLD]
#define CLD 132            // float ld, C stage [64][CLD]
#define SMEMW (64*CLD*4)               // 33792 B (plain wgemm)
#define SMEMF (64*CLD*4 + 128*32*8)    // 66560 B (fusion + readout pairs)

// ---------------- device scratch ----------------
__device__ __align__(256) float  g_h   [(size_t)NN*HID];
__device__ __align__(256) __half g_h16 [(size_t)NN*HID];
__device__ __align__(256) __half g_g16 [(size_t)NN*HID];
__device__ __align__(256) float  g_agg [(size_t)NN*HID];
__device__ __align__(256) float  g_xgat[(size_t)NN*HID];
__device__ __align__(256) float  g_M   [HID*HID];
__device__ __align__(16)  float  g_asrc[(size_t)NN*HEADS];
__device__ __align__(16)  float  g_adst[(size_t)NN*HEADS];
__device__ float g_dinv[NN];
__device__ int   g_cnt_row[NN];
__device__ int   g_cnt_col[NN];
__device__ int   g_rptr[NN+1];
__device__ int   g_cptr[NN+1];
__device__ int   g_rcur[NN];
__device__ int   g_ccur[NN];
__device__ int   g_csr_rc[EE];
__device__ int   g_csr_cs[EE];
__device__ int   g_part[2*NB];
__device__ int   g_shift;

// ---------------- helpers ----------------
__device__ __forceinline__ float wsum(float x){
    #pragma unroll
    for (int o=16;o;o>>=1) x += __shfl_xor_sync(0xffffffffu, x, o);
    return x;
}
__device__ __forceinline__ int wsumi(int x){
    #pragma unroll
    for (int o=16;o;o>>=1) x += __shfl_xor_sync(0xffffffffu, x, o);
    return x;
}
__device__ __forceinline__ float lrelu(float x){ return x > 0.f ? x : NEG * x; }

typedef unsigned long long ull;
__device__ __forceinline__ ull pack2(float x, float y){
    ull r; asm("mov.b64 %0, {%1,%2};" : "=l"(r) : "f"(x), "f"(y)); return r;
}
__device__ __forceinline__ void unpack2(ull v, float &x, float &y){
    asm("mov.b64 {%0,%1}, %2;" : "=f"(x), "=f"(y) : "l"(v));
}
__device__ __forceinline__ void ffma2(ull &d, ull a, ull b){
    asm("fma.rn.f32x2 %0, %1, %2, %0;" : "+l"(d) : "l"(a), "l"(b));
}
__device__ __forceinline__ void acc_h4(uint2 u, float w, float4 &acc){
    float2 f01 = __half22float2(*(const __half2*)&u.x);
    float2 f23 = __half22float2(*(const __half2*)&u.y);
    acc.x = fmaf(w, f01.x, acc.x);
    acc.y = fmaf(w, f01.y, acc.y);
    acc.z = fmaf(w, f23.x, acc.z);
    acc.w = fmaf(w, f23.y, acc.w);
}

// ---------------- init ----------------
__global__ void kInit(const int* ei){
    if (blockIdx.x == 0){
        if (threadIdx.x == 0){
            int acc = 0;
            #pragma unroll 1
            for (int i = 1; i < 128; i += 2) acc |= ei[i];
            g_shift = (acc == 0) ? 1 : 0;
        }
    } else {
        int i = (blockIdx.x-1)*256 + threadIdx.x;
        if (i < NN){ g_cnt_row[i]=0; g_cnt_col[i]=0; }
    }
}

// ---------------- small weight-fold: g_M = Wf1 @ W_e8 ----------------
__global__ void kSmallMM(const float* __restrict__ Wfus, const float* __restrict__ We8){
    int tid = threadIdx.x;
    int half_ = tid >> 7, k = tid & 127;
    int c = blockIdx.x*2 + half_;
    float acc = 0.f;
    #pragma unroll 8
    for (int j = 0; j < 128; j++)
        acc = fmaf(Wfus[c*256 + j], We8[j*128 + k], acc);
    g_M[c*128 + k] = acc;
}

// ---------------- edge loads (x4 vectorized) ----------------
__device__ __forceinline__ void load_edges4(const int* ei, int e0, int sh, int* r, int* c){
    if (sh == 0){
        int4 rr = *(const int4*)(ei + e0);
        int4 cc = *(const int4*)(ei + (size_t)EE + e0);
        r[0]=rr.x; r[1]=rr.y; r[2]=rr.z; r[3]=rr.w;
        c[0]=cc.x; c[1]=cc.y; c[2]=cc.z; c[3]=cc.w;
    } else {
        int4 a = *(const int4*)(ei + 2*(size_t)e0);
        int4 b = *(const int4*)(ei + 2*(size_t)e0 + 4);
        r[0]=a.x; r[1]=a.z; r[2]=b.x; r[3]=b.z;
        int4 d = *(const int4*)(ei + 2*(size_t)EE + 2*(size_t)e0);
        int4 f = *(const int4*)(ei + 2*(size_t)EE + 2*(size_t)e0 + 4);
        c[0]=d.x; c[1]=d.z; c[2]=f.x; c[3]=f.z;
    }
}

__global__ void k_hist(const int* ei){
    int e0 = (blockIdx.x*blockDim.x + threadIdx.x)*4;
    if (e0 >= EE) return;
    int r[4], c[4];
    load_edges4(ei, e0, g_shift, r, c);
    #pragma unroll
    for (int j = 0; j < 4; j++){
        atomicAdd(&g_cnt_row[r[j]], 1);
        atomicAdd(&g_cnt_col[c[j]], 1);
    }
}

__global__ void k_fill(const int* ei){
    int e0 = (blockIdx.x*blockDim.x + threadIdx.x)*4;
    if (e0 >= EE) return;
    int r[4], c[4];
    load_edges4(ei, e0, g_shift, r, c);
    #pragma unroll
    for (int j = 0; j < 4; j++){
        int p = atomicAdd(&g_rcur[r[j]], 1);
        g_csr_rc[p] = c[j];
        int q = atomicAdd(&g_ccur[c[j]], 1);
        g_csr_cs[q] = r[j];
    }
}

// ---------------- scan ----------------
__global__ void kScanP1Dinv(){
    int t = blockIdx.x;
    if (t < 2*NB){
        const int* cnt = (t < NB) ? g_cnt_row : g_cnt_col;
        int i = ((t < NB) ? t : t - NB)*256 + threadIdx.x;
        int v = (i < NN) ? cnt[i] : 0;
        int ws = wsumi(v);
        __shared__ int sums[8];
        int lane = threadIdx.x & 31, warp = threadIdx.x >> 5;
        if (lane == 0) sums[warp] = ws;
        __syncthreads();
        if (threadIdx.x == 0){
            int s = 0;
            #pragma unroll
            for (int w = 0; w < 8; w++) s += sums[w];
            g_part[t] = s;
        }
    } else {
        int i = (t - 2*NB)*256 + threadIdx.x;
        if (i < NN){
            int d = g_cnt_col[i];
            g_dinv[i] = d > 0 ? rsqrtf((float)d) : 0.f;
        }
    }
}

__global__ __launch_bounds__(1024)
void kScanP2(){
    __shared__ int sh[1024];
    int tid = threadIdx.x;
    int half_ = tid >> 9, li = tid & 511;
    int idx = half_ ? NB + li : li;
    int v = (li < NB) ? g_part[idx] : 0;
    sh[tid] = v; __syncthreads();
    #pragma unroll
    for (int off = 1; off < 512; off <<= 1){
        int y = (li >= off) ? sh[tid - off] : 0;
        __syncthreads();
        sh[tid] += y;
        __syncthreads();
    }
    if (li < NB) g_part[idx] = sh[tid] - v;
    if (tid == 0){ g_rptr[NN] = EE; g_cptr[NN] = EE; }
}

__global__ void kScanP3(){
    int t = blockIdx.x;
    int isrow = (t < NB);
    const int* cnt = isrow ? g_cnt_row : g_cnt_col;
    int* ptr = isrow ? g_rptr : g_cptr;
    int* cur = isrow ? g_rcur : g_ccur;
    int i = (isrow ? t : t - NB)*256 + threadIdx.x;
    int v = (i < NN) ? cnt[i] : 0;
    int lane = threadIdx.x & 31, warp = threadIdx.x >> 5;
    int x = v;
    #pragma unroll
    for (int o=1;o<32;o<<=1){
        int y = __shfl_up_sync(0xffffffffu, x, o);
        if (lane >= o) x += y;
    }
    __shared__ int sums[8];
    __shared__ int offs[8];
    if (lane == 31) sums[warp] = x;
    __syncthreads();
    if (threadIdx.x == 0){
        int s = 0;
        #pragma unroll
        for (int w = 0; w < 8; w++){ offs[w] = s; s += sums[w]; }
    }
    __syncthreads();
    int ex = x - v + offs[warp] + g_part[t];
    if (i < NN){ ptr[i] = ex; cur[i] = ex; }
}

// ---------------- WMMA GEMM (plain / att-logit epilogues) ----
template<int EPI>
__global__ __launch_bounds__(256)
void k_wgemm(const float* __restrict__ A0,
             const float* __restrict__ W,
             const float* __restrict__ bias,
             float* __restrict__ C, __half* __restrict__ C16,
             const float* __restrict__ att_s, const float* __restrict__ att_d)
{
    extern __shared__ char smraw[];
    __half* Ah = (__half*)smraw;
    __half* Wh = (__half*)(smraw + 64*ALD*2);
    float*  Cs = (float*)smraw;

    int tid  = threadIdx.x;
    int row0 = blockIdx.x * 64;
    int lane = tid & 31, warp = tid >> 5;
    int wm = warp & 3, wn = warp >> 2;

    wmma::fragment<wmma::accumulator,16,16,16,float> accf[4];
    #pragma unroll
    for (int j = 0; j < 4; j++) wmma::fill_fragment(accf[j], 0.f);

    #pragma unroll
    for (int ch = 0; ch < 2; ch++){
        for (int idx = tid; idx < 128*64; idx += 256){
            int o = idx >> 6, k = idx & 63;
            Wh[o*BLD + k] = __float2half(W[(size_t)o*128 + ch*64 + k]);
        }
        for (int idx = tid; idx < 64*64; idx += 256){
            int r = idx >> 6, k = idx & 63;
            int gr = row0 + r;
            Ah[r*ALD + k] = __float2half(gr < NN ? A0[(size_t)gr*128 + ch*64 + k] : 0.f);
        }
        __syncthreads();
        #pragma unroll
        for (int ks = 0; ks < 64; ks += 16){
            wmma::fragment<wmma::matrix_a,16,16,16,__half,wmma::row_major> af;
            wmma::load_matrix_sync(af, Ah + (wm*16)*ALD + ks, ALD);
            #pragma unroll
            for (int j = 0; j < 4; j++){
                wmma::fragment<wmma::matrix_b,16,16,16,__half,wmma::col_major> bf;
                wmma::load_matrix_sync(bf, Wh + (size_t)(wn*64 + j*16)*BLD + ks, BLD);
                wmma::mma_sync(accf[j], af, bf, accf[j]);
            }
        }
        __syncthreads();
    }

    #pragma unroll
    for (int j = 0; j < 4; j++)
        wmma::store_matrix_sync(Cs + (wm*16)*CLD + wn*64 + j*16, accf[j], CLD,
                                wmma::mem_row_major);
    __syncthreads();

    int r0 = warp * 8;
    float as_[4], ad_[4];
    if (EPI == 2){
        #pragma unroll
        for (int j = 0; j < 4; j++){ as_[j] = att_s[j*32+lane]; ad_[j] = att_d[j*32+lane]; }
    }
    #pragma unroll
    for (int i = 0; i < 8; i++){
        int gr = row0 + r0 + i;
        if (gr >= NN) continue;
        float v[4];
        #pragma unroll
        for (int j = 0; j < 4; j++){
            float b = bias ? bias[lane + 32*j] : 0.f;
            v[j] = Cs[(r0+i)*CLD + lane + 32*j] + b;
        }
        if (C){
            #pragma unroll
            for (int j = 0; j < 4; j++)
                C[(size_t)gr*128 + lane + 32*j] = v[j];
        }
        if (C16){
            #pragma unroll
            for (int j = 0; j < 4; j++)
                C16[(size_t)gr*128 + lane + 32*j] = __float2half(v[j]);
        }
        if (EPI == 2){
            #pragma unroll
            for (int j = 0; j < 4; j++){
                float sj = wsum(v[j]*as_[j]);
                float dj = wsum(v[j]*ad_[j]);
                if (lane == 0){
                    g_asrc[(size_t)gr*4+j] = sj;
                    g_adst[(size_t)gr*4+j] = dj;
                }
            }
        }
    }
}

// ---------------- fusion GEMM (K=256) + residual + LN + ReLU + READOUT ----
__global__ __launch_bounds__(256)
void kFusGemm(const float* __restrict__ A0, const float* __restrict__ A1,
              const float* __restrict__ Wm, const float* __restrict__ Wfus,
              const float* __restrict__ bias,
              const float* __restrict__ res, const float* __restrict__ gamma,
              const float* __restrict__ beta,
              const float* __restrict__ Wr1, const float* __restrict__ br1,
              const float* __restrict__ Wr2, const float* __restrict__ br2,
              float* __restrict__ out)
{
    extern __shared__ char smraw[];
    __half* Ah = (__half*)smraw;
    __half* Wh = (__half*)(smraw + 64*ALD*2);
    float*  Cs = (float*)smraw;
    ull*    Ws2 = (ull*)(smraw + 64*CLD*4);

    int tid  = threadIdx.x;
    int row0 = blockIdx.x * 64;
    int lane = tid & 31, warp = tid >> 5;
    int wm = warp & 3, wn = warp >> 2;

    for (int idx = tid; idx < 128*32; idx += 256){
        int k = idx >> 5, o = idx & 31;
        Ws2[idx] = pack2(Wr1[(size_t)o*128 + k], Wr1[(size_t)(o+32)*128 + k]);
    }

    wmma::fragment<wmma::accumulator,16,16,16,float> accf[4];
    #pragma unroll
    for (int j = 0; j < 4; j++) wmma::fill_fragment(accf[j], 0.f);

    #pragma unroll
    for (int ch = 0; ch < 4; ch++){
        const float* A = (ch >= 2) ? A1 : A0;
        int acol = (ch & 1)*64;
        const float* Wp; int wstride, woff;
        if (ch >= 2){ Wp = Wfus; wstride = 256; woff = 128 + (ch-2)*64; }
        else        { Wp = Wm;   wstride = 128; woff = (ch & 1)*64; }
        for (int idx = tid; idx < 128*64; idx += 256){
            int o = idx >> 6, k = idx & 63;
            Wh[o*BLD + k] = __float2half(Wp[(size_t)o*wstride + woff + k]);
        }
        for (int idx = tid; idx < 64*64; idx += 256){
            int r = idx >> 6, k = idx & 63;
            int gr = row0 + r;
            Ah[r*ALD + k] = __float2half(gr < NN ? A[(size_t)gr*128 + acol + k] : 0.f);
        }
        __syncthreads();
        #pragma unroll
        for (int ks = 0; ks < 64; ks += 16){
            wmma::fragment<wmma::matrix_a,16,16,16,__half,wmma::row_major> af;
            wmma::load_matrix_sync(af, Ah + (wm*16)*ALD + ks, ALD);
            #pragma unroll
            for (int j = 0; j < 4; j++){
                wmma::fragment<wmma::matrix_b,16,16,16,__half,wmma::col_major> bf;
                wmma::load_matrix_sync(bf, Wh + (size_t)(wn*64 + j*16)*BLD + ks, BLD);
                wmma::mma_sync(accf[j], af, bf, accf[j]);
            }
        }
        __syncthreads();
    }

    #pragma unroll
    for (int j = 0; j < 4; j++)
        wmma::store_matrix_sync(Cs + (wm*16)*CLD + wn*64 + j*16, accf[j], CLD,
                                wmma::mem_row_major);
    __syncthreads();

    int r0 = warp * 8;
    float w2a = Wr2[lane], w2b = Wr2[lane+32];
    float b2  = br2[0];
    ull   rb  = pack2(br1[lane], br1[lane+32]);

    #pragma unroll
    for (int i = 0; i < 8; i++){
        int gr = row0 + r0 + i;
        if (gr >= NN) continue;
        float v[4];
        #pragma unroll
        for (int j = 0; j < 4; j++)
            v[j] = Cs[(r0+i)*CLD + lane + 32*j] + bias[lane + 32*j]
                 + res[(size_t)gr*128 + lane + 32*j];
        float s = v[0]+v[1]+v[2]+v[3];
        float mu = wsum(s) * (1.f/128.f);
        float q = 0.f;
        #pragma unroll
        for (int j = 0; j < 4; j++){ float d = v[j]-mu; q = fmaf(d,d,q); }
        float sc = rsqrtf(wsum(q) * (1.f/128.f) + LNEPS);
        #pragma unroll
        for (int j = 0; j < 4; j++){
            int c = lane + 32*j;
            v[j] = fmaxf((v[j]-mu)*sc*gamma[c] + beta[c], 0.f);
        }
        ull racc = rb;
        #pragma unroll 4
        for (int kb = 0; kb < 32; kb++){
            float z0 = __shfl_sync(0xffffffffu, v[0], kb);
            float z1 = __shfl_sync(0xffffffffu, v[1], kb);
            float z2 = __shfl_sync(0xffffffffu, v[2], kb);
            float z3 = __shfl_sync(0xffffffffu, v[3], kb);
            ffma2(racc, pack2(z0,z0), Ws2[(kb     )*32 + lane]);
            ffma2(racc, pack2(z1,z1), Ws2[(kb + 32)*32 + lane]);
            ffma2(racc, pack2(z2,z2), Ws2[(kb + 64)*32 + lane]);
            ffma2(racc, pack2(z3,z3), Ws2[(kb + 96)*32 + lane]);
        }
        float a0, a1; unpack2(racc, a0, a1);
        float pr = fmaf(fmaxf(a0, 0.f), w2a, fmaxf(a1, 0.f) * w2b);
        pr = wsum(pr);
        if (lane == 0)
            out[gr] = 1.f / (1.f + __expf(-(pr + b2)));
    }
}

// ---------------- E8 aggregation body (4-way batched fp16 gathers) --------
__device__ __forceinline__ void e8agg_body(int bid){
    int w = bid*8 + (threadIdx.x >> 5);
    if (w >= NN) return;
    int lane = threadIdx.x & 31;
    int s = g_rptr[w], e = g_rptr[w+1];
    float4 acc = make_float4(0.f,0.f,0.f,0.f);
    int i = s;
    for (; i + 4 <= e; i += 4){
        int c0 = g_csr_rc[i], c1 = g_csr_rc[i+1], c2 = g_csr_rc[i+2], c3 = g_csr_rc[i+3];
        float d0 = g_dinv[c0], d1 = g_dinv[c1], d2 = g_dinv[c2], d3 = g_dinv[c3];
        uint2 q0 = ((const uint2*)(g_h16 + (size_t)c0*HID))[lane];
        uint2 q1 = ((const uint2*)(g_h16 + (size_t)c1*HID))[lane];
        uint2 q2 = ((const uint2*)(g_h16 + (size_t)c2*HID))[lane];
        uint2 q3 = ((const uint2*)(g_h16 + (size_t)c3*HID))[lane];
        acc_h4(q0, d0, acc); acc_h4(q1, d1, acc);
        acc_h4(q2, d2, acc); acc_h4(q3, d3, acc);
    }
    for (; i < e; i++){
        int c = g_csr_rc[i];
        uint2 q = ((const uint2*)(g_h16 + (size_t)c*HID))[lane];
        acc_h4(q, g_dinv[c], acc);
    }
    float du = g_dinv[w];
    float4 o = make_float4(du*acc.x, du*acc.y, du*acc.z, du*acc.w);
    ((float4*)(g_agg + (size_t)w*128))[lane] = o;
}

// ---------------- GAT body (online softmax, 4-way batched gathers) --------
__device__ __forceinline__ void gat_body(int bid, const float* __restrict__ bgat){
    int v = bid*8 + (threadIdx.x >> 5);
    if (v >= NN) return;
    int lane = threadIdx.x & 31;
    int s = g_cptr[v], e = g_cptr[v+1];

    float4 ad = ((const float4*)g_adst)[v];
    float4 asl = ((const float4*)g_asrc)[v];
    float es[4] = { lrelu(asl.x + ad.x), lrelu(asl.y + ad.y),
                    lrelu(asl.z + ad.z), lrelu(asl.w + ad.w) };

    float m[4]  = { es[0], es[1], es[2], es[3] };
    float sm[4] = { 0.f, 0.f, 0.f, 0.f };
    for (int i = s + lane; i < e; i += 32){
        int u = g_csr_cs[i];
        float4 a = ((const float4*)g_asrc)[u];
        float ev[4] = { lrelu(a.x + ad.x), lrelu(a.y + ad.y),
                        lrelu(a.z + ad.z), lrelu(a.w + ad.w) };
        #pragma unroll
        for (int j = 0; j < 4; j++){
            float mn = fmaxf(m[j], ev[j]);
            sm[j] = sm[j]*__expf(m[j]-mn) + __expf(ev[j]-mn);
            m[j] = mn;
        }
    }
    #pragma unroll
    for (int j = 0; j < 4; j++){
        float mj = m[j], sj = sm[j];
        #pragma unroll
        for (int o = 16; o; o >>= 1){
            float m2 = __shfl_xor_sync(0xffffffffu, mj, o);
            float s2 = __shfl_xor_sync(0xffffffffu, sj, o);
            float mn = fmaxf(mj, m2);
            sj = sj*__expf(mj-mn) + s2*__expf(m2-mn);
            mj = mn;
        }
        sj += __expf(es[j]-mj);
        m[j] = mj;
        sm[j] = 1.f/(sj + 1e-16f);
    }

    int hidx = lane >> 3;
    float adh = (hidx==0)?ad.x : (hidx==1)?ad.y : (hidx==2)?ad.z : ad.w;
    float mh  = m[hidx];
    float ih  = sm[hidx];
    float esh = es[hidx];

    float4 acc = make_float4(0.f,0.f,0.f,0.f);
    int i = s;
    for (; i + 4 <= e; i += 4){
        int u0 = g_csr_cs[i],   u1 = g_csr_cs[i+1];
        int u2 = g_csr_cs[i+2], u3 = g_csr_cs[i+3];
        float a0 = g_asrc[(size_t)u0*4 + hidx];
        float a1 = g_asrc[(size_t)u1*4 + hidx];
        float a2 = g_asrc[(size_t)u2*4 + hidx];
        float a3 = g_asrc[(size_t)u3*4 + hidx];
        uint2 q0 = ((const uint2*)(g_g16 + (size_t)u0*HID))[lane];
        uint2 q1 = ((const uint2*)(g_g16 + (size_t)u1*HID))[lane];
        uint2 q2 = ((const uint2*)(g_g16 + (size_t)u2*HID))[lane];
        uint2 q3 = ((const uint2*)(g_g16 + (size_t)u3*HID))[lane];
        float al0 = __expf(lrelu(a0 + adh) - mh) * ih;
        float al1 = __expf(lrelu(a1 + adh) - mh) * ih;
        float al2 = __expf(lrelu(a2 + adh) - mh) * ih;
        float al3 = __expf(lrelu(a3 + adh) - mh) * ih;
        acc_h4(q0, al0, acc); acc_h4(q1, al1, acc);
        acc_h4(q2, al2, acc); acc_h4(q3, al3, acc);
    }
    for (; i < e; i++){
        int u = g_csr_cs[i];
        float a = g_asrc[(size_t)u*4 + hidx];
        uint2 q = ((const uint2*)(g_g16 + (size_t)u*HID))[lane];
        acc_h4(q, __expf(lrelu(a + adh) - mh) * ih, acc);
    }
    {
        float alpha = __expf(esh - mh) * ih;
        uint2 q = ((const uint2*)(g_g16 + (size_t)v*HID))[lane];
        acc_h4(q, alpha, acc);
    }
    float4 b = ((const float4*)bgat)[lane];
    acc.x += b.x; acc.y += b.y; acc.z += b.z; acc.w += b.w;
    ((float4*)(g_xgat + (size_t)v*128))[lane] = acc;
}

__global__ __launch_bounds__(256)
void kAggGat(const float* __restrict__ bgat){
    if (blockIdx.x < AGB) gat_body(blockIdx.x, bgat);
    else                  e8agg_body(blockIdx.x - AGB);
}

// ---------------- host ----------------
extern "C" void kernel_launch(void* const* d_in, const int* in_sizes, int n_in,
                              void* d_out, int out_size)
{
    const float* x       = (const float*)d_in[0];
    const int*   ei      = (const int*)  d_in[1];
    const float* W_emb   = (const float*)d_in[2];
    const float* b_emb   = (const float*)d_in[3];
    const float* W_e8    = (const float*)d_in[4];
    const float* W_gat   = (const float*)d_in[5];
    const float* att_src = (const float*)d_in[6];
    const float* att_dst = (const float*)d_in[7];
    const float* b_gat   = (const float*)d_in[8];
    const float* W_fus   = (const float*)d_in[9];
    const float* b_fus   = (const float*)d_in[10];
    const float* gamma   = (const float*)d_in[11];
    const float* beta    = (const float*)d_in[12];
    const float* W_r1    = (const float*)d_in[13];
    const float* b_r1    = (const float*)d_in[14];
    const float* W_r2    = (const float*)d_in[15];
    const float* b_r2    = (const float*)d_in[16];
    float* out = (float*)d_out;

    float *h, *agg, *xgat, *Mm;
    __half *h16, *g16;
    cudaGetSymbolAddress((void**)&h,    g_h);
    cudaGetSymbolAddress((void**)&h16,  g_h16);
    cudaGetSymbolAddress((void**)&g16,  g_g16);
    cudaGetSymbolAddress((void**)&agg,  g_agg);
    cudaGetSymbolAddress((void**)&xgat, g_xgat);
    cudaGetSymbolAddress((void**)&Mm,   g_M);

    cudaFuncSetAttribute((void*)k_wgemm<0>, cudaFuncAttributeMaxDynamicSharedMemorySize, SMEMW);
    cudaFuncSetAttribute((void*)k_wgemm<2>, cudaFuncAttributeMaxDynamicSharedMemorySize, SMEMW);
    cudaFuncSetAttribute((void*)kFusGemm,   cudaFuncAttributeMaxDynamicSharedMemorySize, SMEMF);

    const int gB = (NN + 63) / 64;

    kInit       <<<1 + NB, 256>>>(ei);                         // 0
    k_hist      <<<(EE/4+255)/256, 256>>>(ei);                 // 1
    kSmallMM    <<<64, 256>>>(W_fus, W_e8);                    // 2
    k_wgemm<0>  <<<gB, 256, SMEMW>>>(x, W_emb, b_emb,
            h, h16, nullptr, nullptr);                         // 3 (profiled)
    kScanP1Dinv <<<2*NB + NB, 256>>>();                        // 4
    kScanP2     <<<1, 1024>>>();                               // 5
    kScanP3     <<<2*NB, 256>>>();                             // 6
    k_fill      <<<(EE/4+255)/256, 256>>>(ei);                 // 7
    k_wgemm<2>  <<<gB, 256, SMEMW>>>(h, W_gat, nullptr,
            nullptr, g16, att_src, att_dst);                   // 8
    kAggGat     <<<2*AGB, 256>>>(b_gat);                       // 9
    kFusGemm    <<<gB, 256, SMEMF>>>(agg, xgat, Mm, W_fus, b_fus,
            h, gamma, beta, W_r1, b_r1, W_r2, b_r2, out);      // 10
}

// round 17
// speedup vs baseline: 1.6187x; 1.1331x over previous
#include <cuda_runtime.h>
#include <cuda_fp16.h>
#include <mma.h>
#include <math.h>
#include <stdint.h>
using namespace nvcuda;

#define NN   100000
#define EE   1600000
#define HID  128
#define HEADS 4
#define NEG  0.2f
#define LNEPS 1e-5f
#define NB   391           // (NN+255)/256
#define AGB  12500         // NN/8 warp-per-node blocks

#define ALD 72             // half ld, A tile [64][ALD]  (row stride 144B = 9*16)
#define BLD 72             // half ld, W tile [128][BLD]
#define CLD 132            // float ld, C stage [64][CLD]
#define SMEMW (64*CLD*4)               // 33792 B
#define SMEMF (64*CLD*4 + 128*32*8)    // 66560 B

// ---------------- device scratch ----------------
__device__ __align__(256) float  g_h   [(size_t)NN*HID];
__device__ __align__(256) __half g_h16 [(size_t)NN*HID];
__device__ __align__(256) __half g_g16 [(size_t)NN*HID];
__device__ __align__(256) float  g_agg [(size_t)NN*HID];
__device__ __align__(256) float  g_xgat[(size_t)NN*HID];
__device__ __align__(256) __half g_M16   [HID*HID];   // fp16 folded Wf1@W_e8
__device__ __align__(256) __half g_Wemb16[HID*HID];
__device__ __align__(256) __half g_Wgat16[HID*HID];
__device__ __align__(256) __half g_Wfus16[HID*HID];   // right half of W_fus
__device__ __align__(16)  float  g_asrc[(size_t)NN*HEADS];
__device__ __align__(16)  float  g_adst[(size_t)NN*HEADS];
__device__ float g_dinv[NN];
__device__ int   g_cnt_row[NN];
__device__ int   g_cnt_col[NN];
__device__ int   g_rptr[NN+1];
__device__ int   g_cptr[NN+1];
__device__ int   g_rcur[NN];
__device__ int   g_ccur[NN];
__device__ int   g_csr_rc[EE];
__device__ int   g_csr_cs[EE];
__device__ int   g_part[2*NB];
__device__ int   g_shift;

// ---------------- helpers ----------------
__device__ __forceinline__ float wsum(float x){
    #pragma unroll
    for (int o=16;o;o>>=1) x += __shfl_xor_sync(0xffffffffu, x, o);
    return x;
}
__device__ __forceinline__ int wsumi(int x){
    #pragma unroll
    for (int o=16;o;o>>=1) x += __shfl_xor_sync(0xffffffffu, x, o);
    return x;
}
__device__ __forceinline__ float lrelu(float x){ return x > 0.f ? x : NEG * x; }

typedef unsigned long long ull;
__device__ __forceinline__ ull pack2(float x, float y){
    ull r; asm("mov.b64 %0, {%1,%2};" : "=l"(r) : "f"(x), "f"(y)); return r;
}
__device__ __forceinline__ void unpack2(ull v, float &x, float &y){
    asm("mov.b64 {%0,%1}, %2;" : "=f"(x), "=f"(y) : "l"(v));
}
__device__ __forceinline__ void ffma2(ull &d, ull a, ull b){
    asm("fma.rn.f32x2 %0, %1, %2, %0;" : "+l"(d) : "l"(a), "l"(b));
}
__device__ __forceinline__ void acc_h4(uint2 u, float w, float4 &acc){
    float2 f01 = __half22float2(*(const __half2*)&u.x);
    float2 f23 = __half22float2(*(const __half2*)&u.y);
    acc.x = fmaf(w, f01.x, acc.x);
    acc.y = fmaf(w, f01.y, acc.y);
    acc.z = fmaf(w, f23.x, acc.z);
    acc.w = fmaf(w, f23.y, acc.w);
}
// 8 floats -> uint4 of halves
__device__ __forceinline__ uint4 f8toh8(float4 f0, float4 f1){
    __half2 h0 = __floats2half2_rn(f0.x, f0.y);
    __half2 h1 = __floats2half2_rn(f0.z, f0.w);
    __half2 h2 = __floats2half2_rn(f1.x, f1.y);
    __half2 h3 = __floats2half2_rn(f1.z, f1.w);
    uint4 o;
    o.x = *(uint32_t*)&h0; o.y = *(uint32_t*)&h1;
    o.z = *(uint32_t*)&h2; o.w = *(uint32_t*)&h3;
    return o;
}

// ---------------- init ----------------
__global__ void kInit(const int* ei){
    if (blockIdx.x == 0){
        if (threadIdx.x == 0){
            int acc = 0;
            #pragma unroll 1
            for (int i = 1; i < 128; i += 2) acc |= ei[i];
            g_shift = (acc == 0) ? 1 : 0;
        }
    } else {
        int i = (blockIdx.x-1)*256 + threadIdx.x;
        if (i < NN){ g_cnt_row[i]=0; g_cnt_col[i]=0; }
    }
}

// ---------------- weight pre-conversion (fp32 -> fp16, once) ----------------
__global__ void kW16(const float* __restrict__ We, const float* __restrict__ Wg,
                     const float* __restrict__ Wf){
    int i = blockIdx.x*256 + threadIdx.x;
    if (i < HID*HID){
        g_Wemb16[i] = __float2half(We[i]);
        g_Wgat16[i] = __float2half(Wg[i]);
        int o = i >> 7, k = i & 127;
        g_Wfus16[i] = __float2half(Wf[(size_t)o*256 + 128 + k]);
    }
}

// ---------------- small weight-fold: g_M16 = fp16(Wf1 @ W_e8) ----------------
__global__ void kSmallMM(const float* __restrict__ Wfus, const float* __restrict__ We8){
    int tid = threadIdx.x;
    int half_ = tid >> 7, k = tid & 127;
    int c = blockIdx.x*2 + half_;
    float acc = 0.f;
    #pragma unroll 8
    for (int j = 0; j < 128; j++)
        acc = fmaf(Wfus[c*256 + j], We8[j*128 + k], acc);
    g_M16[c*128 + k] = __float2half(acc);
}

// ---------------- edge loads (x4 vectorized) ----------------
__device__ __forceinline__ void load_edges4(const int* ei, int e0, int sh, int* r, int* c){
    if (sh == 0){
        int4 rr = *(const int4*)(ei + e0);
        int4 cc = *(const int4*)(ei + (size_t)EE + e0);
        r[0]=rr.x; r[1]=rr.y; r[2]=rr.z; r[3]=rr.w;
        c[0]=cc.x; c[1]=cc.y; c[2]=cc.z; c[3]=cc.w;
    } else {
        int4 a = *(const int4*)(ei + 2*(size_t)e0);
        int4 b = *(const int4*)(ei + 2*(size_t)e0 + 4);
        r[0]=a.x; r[1]=a.z; r[2]=b.x; r[3]=b.z;
        int4 d = *(const int4*)(ei + 2*(size_t)EE + 2*(size_t)e0);
        int4 f = *(const int4*)(ei + 2*(size_t)EE + 2*(size_t)e0 + 4);
        c[0]=d.x; c[1]=d.z; c[2]=f.x; c[3]=f.z;
    }
}

__global__ void k_hist(const int* ei){
    int e0 = (blockIdx.x*blockDim.x + threadIdx.x)*4;
    if (e0 >= EE) return;
    int r[4], c[4];
    load_edges4(ei, e0, g_shift, r, c);
    #pragma unroll
    for (int j = 0; j < 4; j++){
        atomicAdd(&g_cnt_row[r[j]], 1);
        atomicAdd(&g_cnt_col[c[j]], 1);
    }
}

__global__ void k_fill(const int* ei){
    int e0 = (blockIdx.x*blockDim.x + threadIdx.x)*4;
    if (e0 >= EE) return;
    int r[4], c[4];
    load_edges4(ei, e0, g_shift, r, c);
    #pragma unroll
    for (int j = 0; j < 4; j++){
        int p = atomicAdd(&g_rcur[r[j]], 1);
        g_csr_rc[p] = c[j];
        int q = atomicAdd(&g_ccur[c[j]], 1);
        g_csr_cs[q] = r[j];
    }
}

// ---------------- scan ----------------
__global__ void kScanP1Dinv(){
    int t = blockIdx.x;
    if (t < 2*NB){
        const int* cnt = (t < NB) ? g_cnt_row : g_cnt_col;
        int i = ((t < NB) ? t : t - NB)*256 + threadIdx.x;
        int v = (i < NN) ? cnt[i] : 0;
        int ws = wsumi(v);
        __shared__ int sums[8];
        int lane = threadIdx.x & 31, warp = threadIdx.x >> 5;
        if (lane == 0) sums[warp] = ws;
        __syncthreads();
        if (threadIdx.x == 0){
            int s = 0;
            #pragma unroll
            for (int w = 0; w < 8; w++) s += sums[w];
            g_part[t] = s;
        }
    } else {
        int i = (t - 2*NB)*256 + threadIdx.x;
        if (i < NN){
            int d = g_cnt_col[i];
            g_dinv[i] = d > 0 ? rsqrtf((float)d) : 0.f;
        }
    }
}

__global__ __launch_bounds__(1024)
void kScanP2(){
    __shared__ int sh[1024];
    int tid = threadIdx.x;
    int half_ = tid >> 9, li = tid & 511;
    int idx = half_ ? NB + li : li;
    int v = (li < NB) ? g_part[idx] : 0;
    sh[tid] = v; __syncthreads();
    #pragma unroll
    for (int off = 1; off < 512; off <<= 1){
        int y = (li >= off) ? sh[tid - off] : 0;
        __syncthreads();
        sh[tid] += y;
        __syncthreads();
    }
    if (li < NB) g_part[idx] = sh[tid] - v;
    if (tid == 0){ g_rptr[NN] = EE; g_cptr[NN] = EE; }
}

__global__ void kScanP3(){
    int t = blockIdx.x;
    int isrow = (t < NB);
    const int* cnt = isrow ? g_cnt_row : g_cnt_col;
    int* ptr = isrow ? g_rptr : g_cptr;
    int* cur = isrow ? g_rcur : g_ccur;
    int i = (isrow ? t : t - NB)*256 + threadIdx.x;
    int v = (i < NN) ? cnt[i] : 0;
    int lane = threadIdx.x & 31, warp = threadIdx.x >> 5;
    int x = v;
    #pragma unroll
    for (int o=1;o<32;o<<=1){
        int y = __shfl_up_sync(0xffffffffu, x, o);
        if (lane >= o) x += y;
    }
    __shared__ int sums[8];
    __shared__ int offs[8];
    if (lane == 31) sums[warp] = x;
    __syncthreads();
    if (threadIdx.x == 0){
        int s = 0;
        #pragma unroll
        for (int w = 0; w < 8; w++){ offs[w] = s; s += sums[w]; }
    }
    __syncthreads();
    int ex = x - v + offs[warp] + g_part[t];
    if (i < NN){ ptr[i] = ex; cur[i] = ex; }
}

// ---------------- vectorized staging helpers (inside GEMMs) ----------------
__device__ __forceinline__ void stageW(__half* Wh, const __half* W16, int ch, int tid){
    for (int idx = tid; idx < 128*8; idx += 256){
        int o = idx >> 3, kv = idx & 7;
        ((uint4*)(Wh + o*BLD))[kv] =
            ((const uint4*)(W16 + (size_t)o*128 + ch*64))[kv];
    }
}
__device__ __forceinline__ void stageA(__half* Ah, const float* A, int row0, int acol, int tid){
    for (int idx = tid; idx < 64*8; idx += 256){
        int r = idx >> 3, kv = idx & 7;
        int gr = row0 + r;
        uint4 o4;
        if (gr < NN){
            const float4* src = (const float4*)(A + (size_t)gr*128 + acol + kv*8);
            o4 = f8toh8(src[0], src[1]);
        } else o4 = make_uint4(0,0,0,0);
        ((uint4*)(Ah + r*ALD))[kv] = o4;
    }
}

// ---------------- WMMA GEMM (plain / att-logit epilogues) ----
template<int EPI>
__global__ __launch_bounds__(256)
void k_wgemm(const float* __restrict__ A0,
             const __half* __restrict__ W16,
             const float* __restrict__ bias,
             float* __restrict__ C, __half* __restrict__ C16,
             const float* __restrict__ att_s, const float* __restrict__ att_d)
{
    extern __shared__ char smraw[];
    __half* Ah = (__half*)smraw;
    __half* Wh = (__half*)(smraw + 64*ALD*2);
    float*  Cs = (float*)smraw;

    int tid  = threadIdx.x;
    int row0 = blockIdx.x * 64;
    int lane = tid & 31, warp = tid >> 5;
    int wm = warp & 3, wn = warp >> 2;

    wmma::fragment<wmma::accumulator,16,16,16,float> accf[4];
    #pragma unroll
    for (int j = 0; j < 4; j++) wmma::fill_fragment(accf[j], 0.f);

    #pragma unroll
    for (int ch = 0; ch < 2; ch++){
        stageW(Wh, W16, ch, tid);
        stageA(Ah, A0, row0, ch*64, tid);
        __syncthreads();
        #pragma unroll
        for (int ks = 0; ks < 64; ks += 16){
            wmma::fragment<wmma::matrix_a,16,16,16,__half,wmma::row_major> af;
            wmma::load_matrix_sync(af, Ah + (wm*16)*ALD + ks, ALD);
            #pragma unroll
            for (int j = 0; j < 4; j++){
                wmma::fragment<wmma::matrix_b,16,16,16,__half,wmma::col_major> bf;
                wmma::load_matrix_sync(bf, Wh + (size_t)(wn*64 + j*16)*BLD + ks, BLD);
                wmma::mma_sync(accf[j], af, bf, accf[j]);
            }
        }
        __syncthreads();
    }

    #pragma unroll
    for (int j = 0; j < 4; j++)
        wmma::store_matrix_sync(Cs + (wm*16)*CLD + wn*64 + j*16, accf[j], CLD,
                                wmma::mem_row_major);
    __syncthreads();

    int r0 = warp * 8;
    float as_[4], ad_[4];
    if (EPI == 2){
        #pragma unroll
        for (int j = 0; j < 4; j++){ as_[j] = att_s[j*32+lane]; ad_[j] = att_d[j*32+lane]; }
    }
    #pragma unroll
    for (int i = 0; i < 8; i++){
        int gr = row0 + r0 + i;
        if (gr >= NN) continue;
        float v[4];
        #pragma unroll
        for (int j = 0; j < 4; j++){
            float b = bias ? bias[lane + 32*j] : 0.f;
            v[j] = Cs[(r0+i)*CLD + lane + 32*j] + b;
        }
        if (C){
            #pragma unroll
            for (int j = 0; j < 4; j++)
                C[(size_t)gr*128 + lane + 32*j] = v[j];
        }
        if (C16){
            #pragma unroll
            for (int j = 0; j < 4; j++)
                C16[(size_t)gr*128 + lane + 32*j] = __float2half(v[j]);
        }
        if (EPI == 2){
            #pragma unroll
            for (int j = 0; j < 4; j++){
                float sj = wsum(v[j]*as_[j]);
                float dj = wsum(v[j]*ad_[j]);
                if (lane == 0){
                    g_asrc[(size_t)gr*4+j] = sj;
                    g_adst[(size_t)gr*4+j] = dj;
                }
            }
        }
    }
}

// ---------------- fusion GEMM (K=256) + residual + LN + ReLU + READOUT ----
__global__ __launch_bounds__(256)
void kFusGemm(const float* __restrict__ A0, const float* __restrict__ A1,
              const float* __restrict__ bias,
              const float* __restrict__ res, const float* __restrict__ gamma,
              const float* __restrict__ beta,
              const float* __restrict__ Wr1, const float* __restrict__ br1,
              const float* __restrict__ Wr2, const float* __restrict__ br2,
              float* __restrict__ out)
{
    extern __shared__ char smraw[];
    __half* Ah = (__half*)smraw;
    __half* Wh = (__half*)(smraw + 64*ALD*2);
    float*  Cs = (float*)smraw;
    ull*    Ws2 = (ull*)(smraw + 64*CLD*4);

    int tid  = threadIdx.x;
    int row0 = blockIdx.x * 64;
    int lane = tid & 31, warp = tid >> 5;
    int wm = warp & 3, wn = warp >> 2;

    for (int idx = tid; idx < 128*32; idx += 256){
        int k = idx >> 5, o = idx & 31;
        Ws2[idx] = pack2(Wr1[(size_t)o*128 + k], Wr1[(size_t)(o+32)*128 + k]);
    }

    wmma::fragment<wmma::accumulator,16,16,16,float> accf[4];
    #pragma unroll
    for (int j = 0; j < 4; j++) wmma::fill_fragment(accf[j], 0.f);

    #pragma unroll
    for (int ch = 0; ch < 4; ch++){
        const float*  A   = (ch >= 2) ? A1 : A0;
        const __half* W16 = (ch >= 2) ? g_Wfus16 : g_M16;
        int sub = ch & 1;
        stageW(Wh, W16, sub, tid);
        stageA(Ah, A, row0, sub*64, tid);
        __syncthreads();
        #pragma unroll
        for (int ks = 0; ks < 64; ks += 16){
            wmma::fragment<wmma::matrix_a,16,16,16,__half,wmma::row_major> af;
            wmma::load_matrix_sync(af, Ah + (wm*16)*ALD + ks, ALD);
            #pragma unroll
            for (int j = 0; j < 4; j++){
                wmma::fragment<wmma::matrix_b,16,16,16,__half,wmma::col_major> bf;
                wmma::load_matrix_sync(bf, Wh + (size_t)(wn*64 + j*16)*BLD + ks, BLD);
                wmma::mma_sync(accf[j], af, bf, accf[j]);
            }
        }
        __syncthreads();
    }

    #pragma unroll
    for (int j = 0; j < 4; j++)
        wmma::store_matrix_sync(Cs + (wm*16)*CLD + wn*64 + j*16, accf[j], CLD,
                                wmma::mem_row_major);
    __syncthreads();

    int r0 = warp * 8;
    float w2a = Wr2[lane], w2b = Wr2[lane+32];
    float b2  = br2[0];
    ull   rb  = pack2(br1[lane], br1[lane+32]);

    #pragma unroll
    for (int i = 0; i < 8; i++){
        int gr = row0 + r0 + i;
        if (gr >= NN) continue;
        float v[4];
        #pragma unroll
        for (int j = 0; j < 4; j++)
            v[j] = Cs[(r0+i)*CLD + lane + 32*j] + bias[lane + 32*j]
                 + res[(size_t)gr*128 + lane + 32*j];
        float s = v[0]+v[1]+v[2]+v[3];
        float mu = wsum(s) * (1.f/128.f);
        float q = 0.f;
        #pragma unroll
        for (int j = 0; j < 4; j++){ float d = v[j]-mu; q = fmaf(d,d,q); }
        float sc = rsqrtf(wsum(q) * (1.f/128.f) + LNEPS);
        #pragma unroll
        for (int j = 0; j < 4; j++){
            int c = lane + 32*j;
            v[j] = fmaxf((v[j]-mu)*sc*gamma[c] + beta[c], 0.f);
        }
        ull racc = rb;
        #pragma unroll 4
        for (int kb = 0; kb < 32; kb++){
            float z0 = __shfl_sync(0xffffffffu, v[0], kb);
            float z1 = __shfl_sync(0xffffffffu, v[1], kb);
            float z2 = __shfl_sync(0xffffffffu, v[2], kb);
            float z3 = __shfl_sync(0xffffffffu, v[3], kb);
            ffma2(racc, pack2(z0,z0), Ws2[(kb     )*32 + lane]);
            ffma2(racc, pack2(z1,z1), Ws2[(kb + 32)*32 + lane]);
            ffma2(racc, pack2(z2,z2), Ws2[(kb + 64)*32 + lane]);
            ffma2(racc, pack2(z3,z3), Ws2[(kb + 96)*32 + lane]);
        }
        float a0, a1; unpack2(racc, a0, a1);
        float pr = fmaf(fmaxf(a0, 0.f), w2a, fmaxf(a1, 0.f) * w2b);
        pr = wsum(pr);
        if (lane == 0)
            out[gr] = 1.f / (1.f + __expf(-(pr + b2)));
    }
}

// ---------------- E8 aggregation body (4-way batched fp16 gathers) --------
__device__ __forceinline__ void e8agg_body(int bid){
    int w = bid*8 + (threadIdx.x >> 5);
    if (w >= NN) return;
    int lane = threadIdx.x & 31;
    int s = g_rptr[w], e = g_rptr[w+1];
    float4 acc = make_float4(0.f,0.f,0.f,0.f);
    int i = s;
    for (; i + 4 <= e; i += 4){
        int c0 = g_csr_rc[i], c1 = g_csr_rc[i+1], c2 = g_csr_rc[i+2], c3 = g_csr_rc[i+3];
        float d0 = g_dinv[c0], d1 = g_dinv[c1], d2 = g_dinv[c2], d3 = g_dinv[c3];
        uint2 q0 = ((const uint2*)(g_h16 + (size_t)c0*HID))[lane];
        uint2 q1 = ((const uint2*)(g_h16 + (size_t)c1*HID))[lane];
        uint2 q2 = ((const uint2*)(g_h16 + (size_t)c2*HID))[lane];
        uint2 q3 = ((const uint2*)(g_h16 + (size_t)c3*HID))[lane];
        acc_h4(q0, d0, acc); acc_h4(q1, d1, acc);
        acc_h4(q2, d2, acc); acc_h4(q3, d3, acc);
    }
    for (; i < e; i++){
        int c = g_csr_rc[i];
        uint2 q = ((const uint2*)(g_h16 + (size_t)c*HID))[lane];
        acc_h4(q, g_dinv[c], acc);
    }
    float du = g_dinv[w];
    float4 o = make_float4(du*acc.x, du*acc.y, du*acc.z, du*acc.w);
    ((float4*)(g_agg + (size_t)w*128))[lane] = o;
}

// ---------------- GAT body (online softmax, 4-way batched gathers) --------
__device__ __forceinline__ void gat_body(int bid, const float* __restrict__ bgat){
    int v = bid*8 + (threadIdx.x >> 5);
    if (v >= NN) return;
    int lane = threadIdx.x & 31;
    int s = g_cptr[v], e = g_cptr[v+1];

    float4 ad = ((const float4*)g_adst)[v];
    float4 asl = ((const float4*)g_asrc)[v];
    float es[4] = { lrelu(asl.x + ad.x), lrelu(asl.y + ad.y),
                    lrelu(asl.z + ad.z), lrelu(asl.w + ad.w) };

    float m[4]  = { es[0], es[1], es[2], es[3] };
    float sm[4] = { 0.f, 0.f, 0.f, 0.f };
    for (int i = s + lane; i < e; i += 32){
        int u = g_csr_cs[i];
        float4 a = ((const float4*)g_asrc)[u];
        float ev[4] = { lrelu(a.x + ad.x), lrelu(a.y + ad.y),
                        lrelu(a.z + ad.z), lrelu(a.w + ad.w) };
        #pragma unroll
        for (int j = 0; j < 4; j++){
            float mn = fmaxf(m[j], ev[j]);
            sm[j] = sm[j]*__expf(m[j]-mn) + __expf(ev[j]-mn);
            m[j] = mn;
        }
    }
    #pragma unroll
    for (int j = 0; j < 4; j++){
        float mj = m[j], sj = sm[j];
        #pragma unroll
        for (int o = 16; o; o >>= 1){
            float m2 = __shfl_xor_sync(0xffffffffu, mj, o);
            float s2 = __shfl_xor_sync(0xffffffffu, sj, o);
            float mn = fmaxf(mj, m2);
            sj = sj*__expf(mj-mn) + s2*__expf(m2-mn);
            mj = mn;
        }
        sj += __expf(es[j]-mj);
        m[j] = mj;
        sm[j] = 1.f/(sj + 1e-16f);
    }

    int hidx = lane >> 3;
    float adh = (hidx==0)?ad.x : (hidx==1)?ad.y : (hidx==2)?ad.z : ad.w;
    float mh  = m[hidx];
    float ih  = sm[hidx];
    float esh = es[hidx];

    float4 acc = make_float4(0.f,0.f,0.f,0.f);
    int i = s;
    for (; i + 4 <= e; i += 4){
        int u0 = g_csr_cs[i],   u1 = g_csr_cs[i+1];
        int u2 = g_csr_cs[i+2], u3 = g_csr_cs[i+3];
        float a0 = g_asrc[(size_t)u0*4 + hidx];
        float a1 = g_asrc[(size_t)u1*4 + hidx];
        float a2 = g_asrc[(size_t)u2*4 + hidx];
        float a3 = g_asrc[(size_t)u3*4 + hidx];
        uint2 q0 = ((const uint2*)(g_g16 + (size_t)u0*HID))[lane];
        uint2 q1 = ((const uint2*)(g_g16 + (size_t)u1*HID))[lane];
        uint2 q2 = ((const uint2*)(g_g16 + (size_t)u2*HID))[lane];
        uint2 q3 = ((const uint2*)(g_g16 + (size_t)u3*HID))[lane];
        float al0 = __expf(lrelu(a0 + adh) - mh) * ih;
        float al1 = __expf(lrelu(a1 + adh) - mh) * ih;
        float al2 = __expf(lrelu(a2 + adh) - mh) * ih;
        float al3 = __expf(lrelu(a3 + adh) - mh) * ih;
        acc_h4(q0, al0, acc); acc_h4(q1, al1, acc);
        acc_h4(q2, al2, acc); acc_h4(q3, al3, acc);
    }
    for (; i < e; i++){
        int u = g_csr_cs[i];
        float a = g_asrc[(size_t)u*4 + hidx];
        uint2 q = ((const uint2*)(g_g16 + (size_t)u*HID))[lane];
        acc_h4(q, __expf(lrelu(a + adh) - mh) * ih, acc);
    }
    {
        float alpha = __expf(esh - mh) * ih;
        uint2 q = ((const uint2*)(g_g16 + (size_t)v*HID))[lane];
        acc_h4(q, alpha, acc);
    }
    float4 b = ((const float4*)bgat)[lane];
    acc.x += b.x; acc.y += b.y; acc.z += b.z; acc.w += b.w;
    ((float4*)(g_xgat + (size_t)v*128))[lane] = acc;
}

__global__ __launch_bounds__(256)
void kAggGat(const float* __restrict__ bgat){
    if (blockIdx.x < AGB) gat_body(blockIdx.x, bgat);
    else                  e8agg_body(blockIdx.x - AGB);
}

// ---------------- host ----------------
extern "C" void kernel_launch(void* const* d_in, const int* in_sizes, int n_in,
                              void* d_out, int out_size)
{
    const float* x       = (const float*)d_in[0];
    const int*   ei      = (const int*)  d_in[1];
    const float* W_emb   = (const float*)d_in[2];
    const float* b_emb   = (const float*)d_in[3];
    const float* W_e8    = (const float*)d_in[4];
    const float* W_gat   = (const float*)d_in[5];
    const float* att_src = (const float*)d_in[6];
    const float* att_dst = (const float*)d_in[7];
    const float* b_gat   = (const float*)d_in[8];
    const float* W_fus   = (const float*)d_in[9];
    const float* b_fus   = (const float*)d_in[10];
    const float* gamma   = (const float*)d_in[11];
    const float* beta    = (const float*)d_in[12];
    const float* W_r1    = (const float*)d_in[13];
    const float* b_r1    = (const float*)d_in[14];
    const float* W_r2    = (const float*)d_in[15];
    const float* b_r2    = (const float*)d_in[16];
    float* out = (float*)d_out;

    float *h, *agg, *xgat;
    __half *h16, *g16, *We16, *Wg16;
    cudaGetSymbolAddress((void**)&h,    g_h);
    cudaGetSymbolAddress((void**)&h16,  g_h16);
    cudaGetSymbolAddress((void**)&g16,  g_g16);
    cudaGetSymbolAddress((void**)&agg,  g_agg);
    cudaGetSymbolAddress((void**)&xgat, g_xgat);
    cudaGetSymbolAddress((void**)&We16, g_Wemb16);
    cudaGetSymbolAddress((void**)&Wg16, g_Wgat16);

    cudaFuncSetAttribute((void*)k_wgemm<0>, cudaFuncAttributeMaxDynamicSharedMemorySize, SMEMW);
    cudaFuncSetAttribute((void*)k_wgemm<2>, cudaFuncAttributeMaxDynamicSharedMemorySize, SMEMW);
    cudaFuncSetAttribute((void*)kFusGemm,   cudaFuncAttributeMaxDynamicSharedMemorySize, SMEMF);

    const int gB = (NN + 63) / 64;

    kInit       <<<1 + NB, 256>>>(ei);                         // 0
    kW16        <<<64, 256>>>(W_emb, W_gat, W_fus);            // 1
    k_hist      <<<(EE/4+255)/256, 256>>>(ei);                 // 2
    k_wgemm<0>  <<<gB, 256, SMEMW>>>(x, We16, b_emb,
            h, h16, nullptr, nullptr);                         // 3 (profiled)
    kSmallMM    <<<64, 256>>>(W_fus, W_e8);                    // 4
    kScanP1Dinv <<<2*NB + NB, 256>>>();                        // 5
    kScanP2     <<<1, 1024>>>();                               // 6
    kScanP3     <<<2*NB, 256>>>();                             // 7
    k_fill      <<<(EE/4+255)/256, 256>>>(ei);                 // 8
    k_wgemm<2>  <<<gB, 256, SMEMW>>>(h, Wg16, nullptr,
            nullptr, g16, att_src, att_dst);                   // 9
    kAggGat     <<<2*AGB, 256>>>(b_gat);                       // 10
    kFusGemm    <<<gB, 256, SMEMF>>>(agg, xgat, b_fus,
            h, gamma, beta, W_r1, b_r1, W_r2, b_r2, out);      // 11
}